// round 14
// baseline (speedup 1.0000x reference)
#include <cuda_runtime.h>
#include <cuda_fp16.h>
#include <math.h>
#include <stdint.h>

#define NNODES 200000
#define NEDGES 440000
#define NGRAPHS 4096
#define EMBD 300
#define HID 600
#define C4 75
#define C8 38
#define NLAYERS 5
#define NBSCAN ((NNODES + 1 + 1023) / 1024)

#define LDH 320
#define LDT 640
#define MPAD 200064             // 1563 * 128
#define MTOT 1563

// weight buffer offsets (halves)
#define WOFF_W1(l) ((size_t)(l) * 204800)
#define WOFF_W2(l) (1024000 + (size_t)(l) * 204800)
#define WOFF_P1 2048000
#define WOFF_P2 2150400
#define WBUF_SZ 2252800

// ---------------- scratch ----------------
__device__ __align__(16) __half g_ahi[(size_t)MPAD * LDH];   // GEMM1 A operand
__device__ __align__(16) __half g_hh[(size_t)MPAD * LDH];    // h (fp16) / proj lo
__device__ __align__(16) __half g_thi[(size_t)MPAD * LDT];
__device__ __align__(16) __half g_tlo[(size_t)MPAD * LDT];
__device__ __align__(16) __half g_wbuf[WBUF_SZ];
__device__ int   g_cnt[NNODES * 16];
__device__ int   g_rowptr[NNODES + 1];
__device__ int   g_cursor[NNODES + 2];
__device__ int   g_colidx[NEDGES];
__device__ int   g_bsums[256];
__device__ float g_bnsum[EMBD];
__device__ float g_bnss[EMBD];
__device__ float g_bnscale[EMBD];
__device__ float g_bnshift[EMBD];
__device__ float g_pool[NGRAPHS * LDH];
__device__ float g_feat[2 * NGRAPHS * LDH];

// ---------------- helpers ----------------
__device__ __forceinline__ float4 ld4(const float* p) {
    return *reinterpret_cast<const float4*>(p);
}
__device__ __forceinline__ uint32_t smem_u32(const void* p) {
    uint32_t a;
    asm("{ .reg .u64 t; cvta.to.shared.u64 t, %1; cvt.u32.u64 %0, t; }"
        : "=r"(a) : "l"(p));
    return a;
}
__device__ __forceinline__ void cpasync16(uint32_t dst, const void* src) {
    asm volatile("cp.async.cg.shared.global [%0], [%1], 16;"
                 :: "r"(dst), "l"(src));
}

#define LDSM_X4(r0, r1, r2, r3, addr) \
    asm volatile("ldmatrix.sync.aligned.m8n8.x4.shared.b16 {%0,%1,%2,%3}, [%4];" \
                 : "=r"(r0), "=r"(r1), "=r"(r2), "=r"(r3) : "r"(addr))

#define MMA16816(c, a, b0, b1) \
    asm volatile("mma.sync.aligned.m16n8k16.row.col.f32.f16.f16.f32 " \
                 "{%0,%1,%2,%3}, {%4,%5,%6,%7}, {%8,%9}, {%0,%1,%2,%3};" \
                 : "+f"((c)[0]), "+f"((c)[1]), "+f"((c)[2]), "+f"((c)[3]) \
                 : "r"((a)[0]), "r"((a)[1]), "r"((a)[2]), "r"((a)[3]), \
                   "r"(b0), "r"(b1))

#define GTHREADS 512

// ---------------- fused init: weights, table-products, zeroing --------------
__global__ void convert_all_kernel(const float* __restrict__ W1,
                                   const float* __restrict__ W2,
                                   const float* __restrict__ Wp1,
                                   const float* __restrict__ Wp2,
                                   const float* __restrict__ ae1,
                                   const float* __restrict__ ae2,
                                   const float* __restrict__ ee1,
                                   const float* __restrict__ ee2) {
    int gid = blockIdx.x * blockDim.x + threadIdx.x;
    int stride = gridDim.x * blockDim.x;
    for (int i = gid; i < WBUF_SZ; i += stride) {
        float v = 0.f;
        if (i < 1024000) {
            int l = i / 204800, r = i % 204800;
            int n = r / 320, k = r % 320;
            if (k >= 300 && k < 313) continue;  // phase 2 owns these
            if (k < EMBD && n < HID) v = W1[(size_t)l * EMBD * HID + k * HID + n];
        } else if (i < 2048000) {
            int j = i - 1024000;
            int l = j / 204800, r = j % 204800;
            int n = r / 640, k = r % 640;
            if (k < HID && n < EMBD) v = W2[(size_t)l * HID * EMBD + k * EMBD + n];
        } else if (i < 2150400) {
            int r = i - 2048000;
            int n = r / 320, k = r % 320;
            if (k < EMBD && n < EMBD) v = Wp1[k * EMBD + n];
        } else {
            int r = i - 2150400;
            int n = r / 320, k = r % 320;
            if (k < EMBD && n < EMBD) v = Wp2[k * EMBD + n];
        }
        g_wbuf[i] = __float2half_rn(v);
    }
    // table rows @ W1 -> W1 buffer cols 300..312
    for (int t = gid; t < 5 * 640 * 13; t += stride) {
        int l = t / (640 * 13), r = t % (640 * 13);
        int n = r / 13, j = r % 13;
        float v = 0.f;
        if (n < HID && (j < 7 || l == 0)) {
            const float* R1;
            const float* R2 = nullptr;
            if (j < 3) R1 = ee1 + (l * 6 + j) * EMBD;
            else if (j < 6) R1 = ee2 + (l * 3 + (j - 3)) * EMBD;
            else if (j == 6) { R1 = ee1 + (l * 6 + 4) * EMBD; R2 = ee2 + (l * 3) * EMBD; }
            else if (j < 10) R1 = ae1 + (j - 7) * EMBD;
            else R1 = ae2 + (j - 10) * EMBD;
            const float* Wc = W1 + (size_t)l * EMBD * HID + n;
            float acc = 0.f;
            if (R2) {
                for (int k = 0; k < EMBD; k++)
                    acc = fmaf(R1[k] + R2[k], Wc[(size_t)k * HID], acc);
            } else {
                for (int k = 0; k < EMBD; k++)
                    acc = fmaf(R1[k], Wc[(size_t)k * HID], acc);
            }
            v = acc;
        }
        g_wbuf[WOFF_W1(l) + (size_t)n * 320 + 300 + j] = __float2half_rn(v);
    }
    for (int i = gid; i < NNODES * 16; i += stride) g_cnt[i] = 0;
    for (int i = gid; i <= NNODES; i += stride) g_cursor[i] = 0;
    if (gid < EMBD) { g_bnsum[gid] = 0.f; g_bnss[gid] = 0.f; }
}

__global__ void zero_graphbufs_kernel() {
    int i = blockIdx.x * blockDim.x + threadIdx.x;
    int stride = gridDim.x * blockDim.x;
    for (int j = i; j < NNODES * 16; j += stride) g_cnt[j] = 0;
    for (int j = i; j <= NNODES; j += stride) g_cursor[j] = 0;
}

__global__ void convert_split_kernel(const float* __restrict__ src, int n,
                                     __half* __restrict__ hi,
                                     __half* __restrict__ lo) {
    int idx = blockIdx.x * blockDim.x + threadIdx.x;
    if (idx >= n) return;
    float v = src[idx];
    __half h = __float2half_rn(v);
    hi[idx] = h;
    lo[idx] = __float2half_rn(v - __half2float(h));
}

__global__ void convert_h_kernel(const float* __restrict__ src, int n,
                                 __half* __restrict__ hi) {
    int idx = blockIdx.x * blockDim.x + threadIdx.x;
    if (idx >= n) return;
    hi[idx] = __float2half_rn(src[idx]);
}

// ---------------- graph structure ----------------
__global__ void edge_count_kernel(const int* __restrict__ ei,
                                  const int* __restrict__ ea,
                                  const int* __restrict__ x) {
    int e = blockIdx.x * blockDim.x + threadIdx.x;
    if (e >= NEDGES) return;
    int dst = ei[NEDGES + e];
    int src = ei[e];
    atomicAdd(&g_cursor[dst], 1);
    atomicAdd(&g_cnt[dst * 16 + (ea[2 * e] & 3)], 1);
    atomicAdd(&g_cnt[dst * 16 + 4 + (ea[2 * e + 1] & 3)], 1);
    atomicAdd(&g_cnt[dst * 16 + 8 + (x[2 * src] & 3)], 1);
    atomicAdd(&g_cnt[dst * 16 + 12 + (x[2 * src + 1] & 3)], 1);
}

__global__ void coeff_zero_kernel(const int* __restrict__ x) {
    int idx = blockIdx.x * blockDim.x + threadIdx.x;
    if (idx >= NNODES * 80) return;
    int n = idx / 80, c4 = idx % 80;
    size_t o = (size_t)n * LDH + c4 * 4;
    if (c4 < C4) {
        *reinterpret_cast<uint2*>(&g_ahi[o]) = make_uint2(0u, 0u);
        return;
    }
    const int* cnt = g_cnt + n * 16;
    float v0 = 0.f, v1 = 0.f, v2 = 0.f, v3 = 0.f;
    if (c4 == 75) {
        v0 = (float)cnt[0]; v1 = (float)cnt[1];
        v2 = (float)cnt[2]; v3 = (float)cnt[4];
    } else if (c4 == 76) {
        int x0 = x[2 * n] & 3;
        v0 = (float)cnt[5]; v1 = (float)cnt[6];
        v2 = 1.f; v3 = (float)cnt[8] + (x0 == 0 ? 1.f : 0.f);
    } else if (c4 == 77) {
        int x0 = x[2 * n] & 3, x1 = x[2 * n + 1] & 3;
        v0 = (float)cnt[9] + (x0 == 1 ? 1.f : 0.f);
        v1 = (float)cnt[10] + (x0 == 2 ? 1.f : 0.f);
        v2 = (float)cnt[12] + (x1 == 0 ? 1.f : 0.f);
        v3 = (float)cnt[13] + (x1 == 1 ? 1.f : 0.f);
    } else if (c4 == 78) {
        int x1 = x[2 * n + 1] & 3;
        v0 = (float)cnt[14] + (x1 == 2 ? 1.f : 0.f);
    }
    __half2 a = __floats2half2_rn(v0, v1);
    __half2 b = __floats2half2_rn(v2, v3);
    *reinterpret_cast<uint2*>(&g_ahi[o]) =
        make_uint2(*reinterpret_cast<uint32_t*>(&a),
                   *reinterpret_cast<uint32_t*>(&b));
}

__global__ void scan_blocks_kernel() {
    __shared__ int s[1024];
    int tid = threadIdx.x;
    int gid = blockIdx.x * 1024 + tid;
    int v = (gid <= NNODES) ? g_cursor[gid] : 0;
    s[tid] = v;
    __syncthreads();
    for (int off = 1; off < 1024; off <<= 1) {
        int t = (tid >= off) ? s[tid - off] : 0;
        __syncthreads();
        s[tid] += t;
        __syncthreads();
    }
    if (gid <= NNODES) g_rowptr[gid] = s[tid] - v;
    if (tid == 1023) g_bsums[blockIdx.x] = s[1023];
}

__global__ void scan_add_kernel() {
    __shared__ int sbase;
    if (threadIdx.x == 0) {
        int acc = 0;
        for (int i = 0; i < (int)blockIdx.x; i++) acc += g_bsums[i];
        sbase = acc;
    }
    __syncthreads();
    int gid = blockIdx.x * 1024 + threadIdx.x;
    if (gid <= NNODES) {
        int v = g_rowptr[gid] + sbase;
        g_rowptr[gid] = v;
        g_cursor[gid] = v;
    }
}

__global__ void fill_csr_kernel(const int* __restrict__ ei) {
    int e = blockIdx.x * blockDim.x + threadIdx.x;
    if (e >= NEDGES) return;
    int dst = ei[NEDGES + e];
    int pos = atomicAdd(&g_cursor[dst], 1);
    g_colidx[pos] = ei[e];
}

// ---------------- layers 1..4 agg: fp16 gather, 8 cols/thread ---------------
__global__ void agg_kernel() {
    int idx = blockIdx.x * blockDim.x + threadIdx.x;
    if (idx >= NNODES * C8) return;
    int n = idx / C8, c8 = idx % C8;
    int c = c8 * 8;
    int rs = g_rowptr[n], re = g_rowptr[n + 1];
    if (c8 < 37) {
        float4 sc0 = ld4(g_bnscale + c), sh0 = ld4(g_bnshift + c);
        float4 sc1 = ld4(g_bnscale + c + 4), sh1 = ld4(g_bnshift + c + 4);
        float a[8];
#pragma unroll
        for (int k = 0; k < 8; k++) a[k] = 0.f;
        float a2[8];
#pragma unroll
        for (int k = 0; k < 8; k++) a2[k] = 0.f;
        auto addrow = [&](const __half* row, float* acc) {
            uint4 u = *reinterpret_cast<const uint4*>(row);
            float2 f0 = __half22float2(*reinterpret_cast<__half2*>(&u.x));
            float2 f1 = __half22float2(*reinterpret_cast<__half2*>(&u.y));
            float2 f2 = __half22float2(*reinterpret_cast<__half2*>(&u.z));
            float2 f3 = __half22float2(*reinterpret_cast<__half2*>(&u.w));
            acc[0] += fmaxf(fmaf(f0.x, sc0.x, sh0.x), 0.f);
            acc[1] += fmaxf(fmaf(f0.y, sc0.y, sh0.y), 0.f);
            acc[2] += fmaxf(fmaf(f1.x, sc0.z, sh0.z), 0.f);
            acc[3] += fmaxf(fmaf(f1.y, sc0.w, sh0.w), 0.f);
            acc[4] += fmaxf(fmaf(f2.x, sc1.x, sh1.x), 0.f);
            acc[5] += fmaxf(fmaf(f2.y, sc1.y, sh1.y), 0.f);
            acc[6] += fmaxf(fmaf(f3.x, sc1.z, sh1.z), 0.f);
            acc[7] += fmaxf(fmaf(f3.y, sc1.w, sh1.w), 0.f);
        };
        addrow(g_hh + (size_t)n * LDH + c, a);
        int i = rs;
        for (; i + 2 <= re; i += 2) {
            int s0 = g_colidx[i], s1 = g_colidx[i + 1];
            addrow(g_hh + (size_t)s0 * LDH + c, a);
            addrow(g_hh + (size_t)s1 * LDH + c, a2);
        }
        if (i < re) addrow(g_hh + (size_t)g_colidx[i] * LDH + c, a);
#pragma unroll
        for (int k = 0; k < 8; k++) a[k] += a2[k];
        __half2 o0 = __floats2half2_rn(a[0], a[1]);
        __half2 o1 = __floats2half2_rn(a[2], a[3]);
        __half2 o2 = __floats2half2_rn(a[4], a[5]);
        __half2 o3 = __floats2half2_rn(a[6], a[7]);
        uint4 out;
        out.x = *reinterpret_cast<uint32_t*>(&o0);
        out.y = *reinterpret_cast<uint32_t*>(&o1);
        out.z = *reinterpret_cast<uint32_t*>(&o2);
        out.w = *reinterpret_cast<uint32_t*>(&o3);
        *reinterpret_cast<uint4*>(&g_ahi[(size_t)n * LDH + c]) = out;
    } else {
        float4 sc0 = ld4(g_bnscale + c), sh0 = ld4(g_bnshift + c);
        float a[4] = {0.f, 0.f, 0.f, 0.f};
        auto addrow4 = [&](const __half* row) {
            uint2 u = *reinterpret_cast<const uint2*>(row);
            float2 f0 = __half22float2(*reinterpret_cast<__half2*>(&u.x));
            float2 f1 = __half22float2(*reinterpret_cast<__half2*>(&u.y));
            a[0] += fmaxf(fmaf(f0.x, sc0.x, sh0.x), 0.f);
            a[1] += fmaxf(fmaf(f0.y, sc0.y, sh0.y), 0.f);
            a[2] += fmaxf(fmaf(f1.x, sc0.z, sh0.z), 0.f);
            a[3] += fmaxf(fmaf(f1.y, sc0.w, sh0.w), 0.f);
        };
        addrow4(g_hh + (size_t)n * LDH + c);
        for (int i = rs; i < re; i++)
            addrow4(g_hh + (size_t)g_colidx[i] * LDH + c);
        __half2 o0 = __floats2half2_rn(a[0], a[1]);
        __half2 o1 = __floats2half2_rn(a[2], a[3]);
        uint2 out;
        out.x = *reinterpret_cast<uint32_t*>(&o0);
        out.y = *reinterpret_cast<uint32_t*>(&o1);
        *reinterpret_cast<uint2*>(&g_ahi[(size_t)n * LDH + c]) = out;
    }
}

// ---------------- stage loader, templated N-tile -----------------------------
template <int TERMS, int NT>
__device__ __forceinline__ void gemm_load_stage(
    uint32_t sbase, int tid, int m0, int n0, int k0,
    const __half* Ahi, const __half* Alo, int lda,
    const __half* Bh, int Kpad, int Npad) {
    constexpr uint32_t SMB = TERMS * 16384;
#pragma unroll
    for (int it = 0; it < 2; it++) {
        int L = it * GTHREADS + tid;
        int row = L >> 3, j = L & 7;
        uint32_t soff = (uint32_t)row * 128 +
                        (((uint32_t)j * 16) ^ (((uint32_t)(row & 7)) << 4));
        size_t aoff = (size_t)(m0 + row) * lda + k0 + j * 8;
        cpasync16(sbase + soff, Ahi + aoff);
        if (TERMS == 2) cpasync16(sbase + 16384 + soff, Alo + aoff);
    }
#pragma unroll
    for (int it = 0; it < NT / 64; it++) {
        int L = it * GTHREADS + tid;
        int row = L >> 3, j = L & 7;
        uint32_t soff = (uint32_t)row * 128 +
                        (((uint32_t)j * 16) ^ (((uint32_t)(row & 7)) << 4));
        int brow = n0 + row;
        brow = brow < Npad ? brow : Npad - 1;
        size_t boff = (size_t)brow * Kpad + k0 + j * 8;
        cpasync16(sbase + SMB + soff, Bh + boff);
    }
    asm volatile("cp.async.commit_group;" ::: "memory");
}

// ---------------- persistent fp16 mma.sync GEMM, tile 128M x NT-N -----------
// Each CTA walks m-blocks (blockIdx.y, += gridDim.y) with a continuous
// 3-stage cp.async ring across block boundaries. 512 threads, 4m x 4n warps.
template <int RELU, int SPLITOUT, int STATS, int TERMS, int NT>
__global__ void __launch_bounds__(GTHREADS, 1)
mma_gemm(const __half* __restrict__ Ahi, const __half* __restrict__ Alo,
         int lda, int Kpad, int mblocks,
         const __half* __restrict__ Bh, int Npad,
         const float* __restrict__ bias, float scale,
         float* __restrict__ C, __half* __restrict__ Chi,
         __half* __restrict__ Clo, int ldc, int Nreal) {
    extern __shared__ char smem[];
    constexpr int JN = NT / 32;
    constexpr int NQ = NT / 64;
    constexpr uint32_t SMB = TERMS * 16384;
    constexpr uint32_t STG = SMB + NT * 128;
    uint32_t sb = smem_u32(smem);
    int tid = threadIdx.x;
    int n0 = blockIdx.x * NT;
    int nchunks = Kpad >> 6;

    int nmb = 0;
    for (int t = blockIdx.y; t < mblocks; t += gridDim.y) nmb++;
    if (nmb == 0) return;
    int tc = nmb * nchunks;

    auto m0_of = [&](int gc) {
        return ((int)blockIdx.y + (gc / nchunks) * (int)gridDim.y) * 128;
    };
    auto k0_of = [&](int gc) { return (gc % nchunks) * 64; };

    gemm_load_stage<TERMS, NT>(sb, tid, m0_of(0), n0, k0_of(0),
                               Ahi, Alo, lda, Bh, Kpad, Npad);
    if (tc > 1)
        gemm_load_stage<TERMS, NT>(sb + STG, tid, m0_of(1), n0, k0_of(1),
                                   Ahi, Alo, lda, Bh, Kpad, Npad);
    else
        asm volatile("cp.async.commit_group;" ::: "memory");

    int lane = tid & 31, wid = tid >> 5;
    int wm = wid & 3, wn = wid >> 2;

    float acc[2][JN][4];
#pragma unroll
    for (int i = 0; i < 2; i++)
#pragma unroll
        for (int j = 0; j < JN; j++)
#pragma unroll
            for (int r = 0; r < 4; r++) acc[i][j][r] = 0.f;

    uint32_t mask = ((uint32_t)(lane & 7)) << 4;
    uint32_t a_row_off[2];
#pragma unroll
    for (int i = 0; i < 2; i++)
        a_row_off[i] = (uint32_t)(wm * 32 + i * 16 + (lane & 15)) * 128;
    uint32_t a_kb_base = (uint32_t)((lane >> 4) * 16);
    int g = lane >> 3;
    uint32_t b_row_base = (uint32_t)(wn * (NT / 4) + (g >> 1) * 8 + (lane & 7));
    uint32_t b_kb_base = (uint32_t)((g & 1) * 16);

    int slot = 0;
    for (int gc = 0; gc < tc; gc++) {
        asm volatile("cp.async.wait_group 1;" ::: "memory");
        __syncthreads();
        if (gc + 2 < tc) {
            int ns = slot + 2;
            if (ns >= 3) ns -= 3;
            gemm_load_stage<TERMS, NT>(sb + (uint32_t)ns * STG, tid,
                                       m0_of(gc + 2), n0, k0_of(gc + 2),
                                       Ahi, Alo, lda, Bh, Kpad, Npad);
        } else {
            asm volatile("cp.async.commit_group;" ::: "memory");
        }
        uint32_t st = sb + (uint32_t)slot * STG;
#pragma unroll
        for (int s = 0; s < 4; s++) {
            uint32_t akb = (a_kb_base + s * 32) ^ mask;
            uint32_t bkb = (b_kb_base + s * 32) ^ mask;
            uint32_t ah[2][4], al[2][4];
#pragma unroll
            for (int i = 0; i < 2; i++) {
                LDSM_X4(ah[i][0], ah[i][1], ah[i][2], ah[i][3],
                        st + a_row_off[i] + akb);
                if (TERMS == 2)
                    LDSM_X4(al[i][0], al[i][1], al[i][2], al[i][3],
                            st + 16384 + a_row_off[i] + akb);
            }
#pragma unroll
            for (int q = 0; q < NQ; q++) {
                uint32_t broff = (b_row_base + q * 16) * 128;
                uint32_t bh[4];
                LDSM_X4(bh[0], bh[1], bh[2], bh[3], st + SMB + broff + bkb);
#pragma unroll
                for (int i = 0; i < 2; i++) {
                    MMA16816(acc[i][2 * q], ah[i], bh[0], bh[1]);
                    if (TERMS == 2)
                        MMA16816(acc[i][2 * q], al[i], bh[0], bh[1]);
                    MMA16816(acc[i][2 * q + 1], ah[i], bh[2], bh[3]);
                    if (TERMS == 2)
                        MMA16816(acc[i][2 * q + 1], al[i], bh[2], bh[3]);
                }
            }
        }
        if (++slot == 3) slot = 0;

        // ---- per-m-block epilogue after its last chunk (registers only) ----
        if (gc % nchunks == nchunks - 1) {
            int m0 = m0_of(gc);
#pragma unroll
            for (int j = 0; j < JN; j++) {
                int col = n0 + wn * (NT / 4) + j * 8 + (lane & 3) * 2;
                float b0 = 0.f, b1 = 0.f;
                if (bias != nullptr) {
                    b0 = (col < Nreal) ? bias[col] : 0.f;
                    b1 = (col + 1 < Nreal) ? bias[col + 1] : 0.f;
                }
                float s0 = 0.f, s1 = 0.f, q0 = 0.f, q1 = 0.f;
#pragma unroll
                for (int i = 0; i < 2; i++) {
                    int r0 = m0 + wm * 32 + i * 16 + (lane >> 2);
                    float v00 = (col < Nreal) ? (acc[i][j][0] + b0) * scale : 0.f;
                    float v01 = (col + 1 < Nreal) ? (acc[i][j][1] + b1) * scale : 0.f;
                    float v10 = (col < Nreal) ? (acc[i][j][2] + b0) * scale : 0.f;
                    float v11 = (col + 1 < Nreal) ? (acc[i][j][3] + b1) * scale : 0.f;
                    if (RELU) {
                        v00 = fmaxf(v00, 0.f); v01 = fmaxf(v01, 0.f);
                        v10 = fmaxf(v10, 0.f); v11 = fmaxf(v11, 0.f);
                    }
                    if (STATS) {
                        bool ok0 = (r0 < NNODES), ok1 = (r0 + 8 < NNODES);
                        s0 += (ok0 ? v00 : 0.f) + (ok1 ? v10 : 0.f);
                        s1 += (ok0 ? v01 : 0.f) + (ok1 ? v11 : 0.f);
                        q0 += (ok0 ? v00 * v00 : 0.f) + (ok1 ? v10 * v10 : 0.f);
                        q1 += (ok0 ? v01 * v01 : 0.f) + (ok1 ? v11 * v11 : 0.f);
                    }
                    if (col < ldc) {
                        if (SPLITOUT >= 1) {
                            __half h00 = __float2half_rn(v00);
                            __half h01 = __float2half_rn(v01);
                            __half h10 = __float2half_rn(v10);
                            __half h11 = __float2half_rn(v11);
                            *reinterpret_cast<__half2*>(Chi + (size_t)r0 * ldc + col) =
                                __halves2half2(h00, h01);
                            *reinterpret_cast<__half2*>(Chi + (size_t)(r0 + 8) * ldc + col) =
                                __halves2half2(h10, h11);
                            if (SPLITOUT == 1) {
                                __half2 ll0 = __halves2half2(
                                    __float2half_rn(v00 - __half2float(h00)),
                                    __float2half_rn(v01 - __half2float(h01)));
                                __half2 ll1 = __halves2half2(
                                    __float2half_rn(v10 - __half2float(h10)),
                                    __float2half_rn(v11 - __half2float(h11)));
                                *reinterpret_cast<__half2*>(Clo + (size_t)r0 * ldc + col) = ll0;
                                *reinterpret_cast<__half2*>(Clo + (size_t)(r0 + 8) * ldc + col) = ll1;
                            }
                        } else {
                            *reinterpret_cast<float2*>(C + (size_t)r0 * ldc + col) =
                                make_float2(v00, v01);
                            *reinterpret_cast<float2*>(C + (size_t)(r0 + 8) * ldc + col) =
                                make_float2(v10, v11);
                        }
                    }
                }
                if (STATS) {
#pragma unroll
                    for (int o = 16; o >= 4; o >>= 1) {
                        s0 += __shfl_down_sync(0xffffffffu, s0, o);
                        s1 += __shfl_down_sync(0xffffffffu, s1, o);
                        q0 += __shfl_down_sync(0xffffffffu, q0, o);
                        q1 += __shfl_down_sync(0xffffffffu, q1, o);
                    }
                    if (lane < 4 && col < Nreal) {
                        atomicAdd(&g_bnsum[col], s0);
                        atomicAdd(&g_bnsum[col + 1], s1);
                        atomicAdd(&g_bnss[col], q0);
                        atomicAdd(&g_bnss[col + 1], q1);
                    }
                }
            }
#pragma unroll
            for (int i = 0; i < 2; i++)
#pragma unroll
                for (int j = 0; j < JN; j++)
#pragma unroll
                    for (int r = 0; r < 4; r++) acc[i][j][r] = 0.f;
        }
    }
}

// ---------------- BatchNorm finalize (self-resets stats) ----------------
__global__ void bn_finalize_kernel(const float* __restrict__ gamma,
                                   const float* __restrict__ beta) {
    int c = threadIdx.x;
    if (c >= EMBD) return;
    float sum = g_bnsum[c], ss = g_bnss[c];
    float mean = sum * (1.0f / NNODES);
    float var = ss * (1.0f / NNODES) - mean * mean;
    float rs = rsqrtf(var + 1e-5f);
    float s = rs * gamma[c];
    g_bnscale[c] = s;
    g_bnshift[c] = beta[c] - mean * s;
    g_bnsum[c] = 0.f;
    g_bnss[c] = 0.f;
}

// ---------------- segment pooling (fp16 h; BN folded in) -------------------
__global__ void pool_seg_kernel(const int* __restrict__ bi) {
    __shared__ int s_lo, s_hi;
    int g = blockIdx.x;
    if (threadIdx.x == 0) {
        int lo = 0, hi = NNODES;
        while (lo < hi) { int m = (lo + hi) >> 1; if (bi[m] < g) lo = m + 1; else hi = m; }
        s_lo = lo;
        int lo2 = lo, hi2 = NNODES;
        while (lo2 < hi2) { int m = (lo2 + hi2) >> 1; if (bi[m] < g + 1) lo2 = m + 1; else hi2 = m; }
        s_hi = lo2;
    }
    __syncthreads();
    int lo = s_lo, hi = s_hi;
    float inv = 1.0f / fmaxf((float)(hi - lo), 1.0f);
    int c0 = threadIdx.x, c1 = c0 + 128, c2 = c0 + 256;
    float a0 = 0.f, a1 = 0.f, a2 = 0.f;
    for (int r = lo; r < hi; r++) {
        const __half* row = g_hh + (size_t)r * LDH;
        a0 += __half2float(row[c0]);
        a1 += __half2float(row[c1]);
        if (c2 < EMBD) a2 += __half2float(row[c2]);
    }
    float* dst = g_pool + (size_t)g * LDH;
    dst[c0] = fmaf(a0 * inv, g_bnscale[c0], g_bnshift[c0]);
    dst[c1] = fmaf(a1 * inv, g_bnscale[c1], g_bnshift[c1]);
    if (c2 < EMBD) dst[c2] = fmaf(a2 * inv, g_bnscale[c2], g_bnshift[c2]);
    else if (c2 < LDH) dst[c2] = 0.f;
}

// ---------------- L2 row normalize ----------------
__global__ void normalize_kernel(float* __restrict__ f) {
    __shared__ float red[4];
    size_t r = blockIdx.x;
    float* row = f + r * LDH;
    float ss = 0.f;
    for (int c = threadIdx.x; c < EMBD; c += 128) {
        float v = row[c];
        ss += v * v;
    }
    for (int o = 16; o; o >>= 1) ss += __shfl_down_sync(0xffffffffu, ss, o);
    if ((threadIdx.x & 31) == 0) red[threadIdx.x >> 5] = ss;
    __syncthreads();
    if (threadIdx.x == 0) red[0] = rsqrtf(red[0] + red[1] + red[2] + red[3]);
    __syncthreads();
    float s = red[0];
    for (int c = threadIdx.x; c < EMBD; c += 128) row[c] *= s;
}

__global__ void labels_kernel(float* __restrict__ out, int extra) {
    int i = blockIdx.x * blockDim.x + threadIdx.x;
    if (i < extra) out[i] = (float)i;
}

// ---------------- host orchestration ----------------
extern "C" void kernel_launch(void* const* d_in, const int* in_sizes, int n_in,
                              void* d_out, int out_size) {
    const float* ae1 = (const float*)d_in[8];
    const float* ae2 = (const float*)d_in[9];
    const float* ee1 = (const float*)d_in[10];
    const float* ee2 = (const float*)d_in[11];
    const float* W1 = (const float*)d_in[12];
    const float* bm1 = (const float*)d_in[13];
    const float* W2 = (const float*)d_in[14];
    const float* bm2 = (const float*)d_in[15];
    const float* gamma = (const float*)d_in[16];
    const float* beta = (const float*)d_in[17];
    const float* bp1 = (const float*)d_in[19];
    const float* bp2 = (const float*)d_in[21];

    float *pool, *feat;
    __half *ahi, *hh, *thi, *tlo, *wbuf;
    cudaGetSymbolAddress((void**)&pool, g_pool);
    cudaGetSymbolAddress((void**)&feat, g_feat);
    cudaGetSymbolAddress((void**)&ahi, g_ahi);
    cudaGetSymbolAddress((void**)&hh, g_hh);
    cudaGetSymbolAddress((void**)&thi, g_thi);
    cudaGetSymbolAddress((void**)&tlo, g_tlo);
    cudaGetSymbolAddress((void**)&wbuf, g_wbuf);

    const int SM_G1 = 3 * (16384 + 320 * 128);   // TERMS=1, NT=320
    const int SM_P = 3 * (32768 + 320 * 128);    // TERMS=2, NT=320
    const int SM_L = 3 * (32768 + 256 * 128);    // TERMS=2, NT=256
    cudaFuncSetAttribute(mma_gemm<1, 2, 0, 1, 320>,
                         cudaFuncAttributeMaxDynamicSharedMemorySize, SM_G1);
    cudaFuncSetAttribute(mma_gemm<0, 2, 1, 1, 320>,
                         cudaFuncAttributeMaxDynamicSharedMemorySize, SM_G1);
    cudaFuncSetAttribute(mma_gemm<1, 1, 0, 2, 320>,
                         cudaFuncAttributeMaxDynamicSharedMemorySize, SM_P);
    cudaFuncSetAttribute(mma_gemm<0, 0, 0, 2, 320>,
                         cudaFuncAttributeMaxDynamicSharedMemorySize, SM_P);
    cudaFuncSetAttribute(mma_gemm<0, 0, 0, 2, 256>,
                         cudaFuncAttributeMaxDynamicSharedMemorySize, SM_L);

    const int GN38 = (NNODES * C8 + 255) / 256;
    const int GN80 = (NNODES * 80 + 255) / 256;
    const int GE = (NEDGES + 255) / 256;
    const int GP = (NGRAPHS * LDH + 255) / 256;

    convert_all_kernel<<<2048, 256>>>(W1, W2, (const float*)d_in[18],
                                      (const float*)d_in[20],
                                      ae1, ae2, ee1, ee2);

    for (int enc = 0; enc < 2; enc++) {
        const int* x = (const int*)d_in[enc * 4 + 0];
        const int* ei = (const int*)d_in[enc * 4 + 1];
        const int* ea = (const int*)d_in[enc * 4 + 2];
        const int* bi = (const int*)d_in[enc * 4 + 3];

        if (enc == 1) zero_graphbufs_kernel<<<2048, 256>>>();
        edge_count_kernel<<<GE, 256>>>(ei, ea, x);
        coeff_zero_kernel<<<GN80, 256>>>(x);

        for (int l = 0; l < NLAYERS; l++) {
            if (l > 0) agg_kernel<<<GN38, 256>>>();

            // GEMM1 (persistent): A @ W1ext -> thi, relu. 148 CTAs, 21 mb each.
            mma_gemm<1, 2, 0, 1, 320><<<dim3(2, 74), GTHREADS, SM_G1>>>(
                ahi, nullptr, 320, 320, MTOT, wbuf + WOFF_W1(l), 640,
                bm1 + l * HID, 1.0f, nullptr, thi, nullptr, LDT, HID);

            if (l == 0) {
                scan_blocks_kernel<<<NBSCAN, 1024>>>();
                scan_add_kernel<<<NBSCAN, 1024>>>();
                fill_csr_kernel<<<GE, 256>>>(ei);
            }

            // GEMM2 (persistent): thi @ W2 -> h fp16 + stats. 148 CTAs.
            mma_gemm<0, 2, 1, 1, 320><<<dim3(1, 148), GTHREADS, SM_G1>>>(
                thi, nullptr, LDT, 640, MTOT, wbuf + WOFF_W2(l), 320,
                bm2 + l * EMBD, 1.0f, nullptr, hh, nullptr, LDH, EMBD);
            bn_finalize_kernel<<<1, 512>>>(gamma + l * EMBD, beta + l * EMBD);
        }

        pool_seg_kernel<<<NGRAPHS, 128>>>(bi);

        // projection head (M=4096), 2-term split for precision
        convert_split_kernel<<<GP, 256>>>(pool, NGRAPHS * LDH, ahi, hh);
        mma_gemm<1, 1, 0, 2, 320><<<dim3(1, 32), GTHREADS, SM_P>>>(
            ahi, hh, 320, 320, 32, wbuf + WOFF_P1, 320, bp1, 1.0f,
            nullptr, thi, tlo, 320, EMBD);
        mma_gemm<0, 0, 0, 2, 320><<<dim3(1, 32), GTHREADS, SM_P>>>(
            thi, tlo, 320, 320, 32, wbuf + WOFF_P2, 320, bp2, 1.0f,
            feat + (size_t)enc * NGRAPHS * LDH, nullptr, nullptr, LDH, EMBD);
    }

    normalize_kernel<<<2 * NGRAPHS, 128>>>(feat);

    // logits = 25 * f0 @ f1^T : f0 split (A, 2-term), f1 single fp16 (B)
    convert_split_kernel<<<GP, 256>>>(feat, NGRAPHS * LDH, ahi, hh);
    convert_h_kernel<<<GP, 256>>>(feat + (size_t)NGRAPHS * LDH,
                                  NGRAPHS * LDH, thi);
    mma_gemm<0, 0, 0, 2, 256><<<dim3(NGRAPHS / 256, 32), GTHREADS, SM_L>>>(
        ahi, hh, 320, 320, 32, thi, NGRAPHS,
        nullptr, 25.0f, (float*)d_out, nullptr, nullptr, NGRAPHS, NGRAPHS);

    long long logits_elems = (long long)NGRAPHS * NGRAPHS;
    int extra = (int)((long long)out_size - logits_elems);
    if (extra > 0)
        labels_kernel<<<(extra + 255) / 256, 256>>>(
            (float*)d_out + logits_elems, extra);
}

// round 15
// speedup vs baseline: 1.0537x; 1.0537x over previous
#include <cuda_runtime.h>
#include <cuda_fp16.h>
#include <math.h>
#include <stdint.h>

#define NNODES 200000
#define NEDGES 440000
#define NGRAPHS 4096
#define EMBD 300
#define HID 600
#define C8 38
#define NLAYERS 5

#define LDH 320
#define LDT 640
#define MPAD 200064             // 1563 * 128
#define MTOT 1563
#define M2 (2 * MPAD)
#define NB2 ((M2 + 1 + 1023) / 1024)   // scan blocks over 2*MPAD+1

// weight buffer offsets (halves)
#define WOFF_W1(l) ((size_t)(l) * 204800)
#define WOFF_W2(l) (1024000 + (size_t)(l) * 204800)
#define WOFF_P1 2048000
#define WOFF_P2 2150400
#define WBUF_SZ 2252800

// ---------------- scratch (both encoders batched) ----------------
__device__ __align__(16) __half g_ahi[(size_t)M2 * LDH];
__device__ __align__(16) __half g_hh[(size_t)M2 * LDH];
__device__ __align__(16) __half g_thi[(size_t)M2 * LDT];
__device__ __align__(16) __half g_phi[2 * NGRAPHS * LDH];
__device__ __align__(16) __half g_plo[2 * NGRAPHS * LDH];
__device__ __align__(16) __half g_qlo[2 * NGRAPHS * LDH];
__device__ __align__(16) __half g_wbuf[WBUF_SZ];
__device__ int   g_cnt[2 * NNODES * 16];
__device__ int   g_rowptr[M2 + 2];
__device__ int   g_cursor[M2 + 2];
__device__ int   g_colidx[2 * NEDGES];
__device__ int   g_bsums[512];
__device__ float g_bnsum[2 * EMBD];
__device__ float g_bnss[2 * EMBD];
__device__ float g_bnscale[2 * 320];
__device__ float g_bnshift[2 * 320];
__device__ float g_pool[2 * NGRAPHS * LDH];
__device__ float g_feat[2 * NGRAPHS * LDH];

// ---------------- helpers ----------------
__device__ __forceinline__ float4 ld4(const float* p) {
    return *reinterpret_cast<const float4*>(p);
}
__device__ __forceinline__ uint32_t smem_u32(const void* p) {
    uint32_t a;
    asm("{ .reg .u64 t; cvta.to.shared.u64 t, %1; cvt.u32.u64 %0, t; }"
        : "=r"(a) : "l"(p));
    return a;
}
__device__ __forceinline__ void cpasync16(uint32_t dst, const void* src) {
    asm volatile("cp.async.cg.shared.global [%0], [%1], 16;"
                 :: "r"(dst), "l"(src));
}

#define LDSM_X4(r0, r1, r2, r3, addr) \
    asm volatile("ldmatrix.sync.aligned.m8n8.x4.shared.b16 {%0,%1,%2,%3}, [%4];" \
                 : "=r"(r0), "=r"(r1), "=r"(r2), "=r"(r3) : "r"(addr))

#define MMA16816(c, a, b0, b1) \
    asm volatile("mma.sync.aligned.m16n8k16.row.col.f32.f16.f16.f32 " \
                 "{%0,%1,%2,%3}, {%4,%5,%6,%7}, {%8,%9}, {%0,%1,%2,%3};" \
                 : "+f"((c)[0]), "+f"((c)[1]), "+f"((c)[2]), "+f"((c)[3]) \
                 : "r"((a)[0]), "r"((a)[1]), "r"((a)[2]), "r"((a)[3]), \
                   "r"(b0), "r"(b1))

#define GTHREADS 512

// ---------------- fused init: weights, table-products, zeroing --------------
__global__ void convert_all_kernel(const float* __restrict__ W1,
                                   const float* __restrict__ W2,
                                   const float* __restrict__ Wp1,
                                   const float* __restrict__ Wp2,
                                   const float* __restrict__ ae1,
                                   const float* __restrict__ ae2,
                                   const float* __restrict__ ee1,
                                   const float* __restrict__ ee2) {
    int gid = blockIdx.x * blockDim.x + threadIdx.x;
    int stride = gridDim.x * blockDim.x;
    for (int i = gid; i < WBUF_SZ; i += stride) {
        float v = 0.f;
        if (i < 1024000) {
            int l = i / 204800, r = i % 204800;
            int n = r / 320, k = r % 320;
            if (k >= 300 && k < 313) continue;  // phase 2 owns these
            if (k < EMBD && n < HID) v = W1[(size_t)l * EMBD * HID + k * HID + n];
        } else if (i < 2048000) {
            int j = i - 1024000;
            int l = j / 204800, r = j % 204800;
            int n = r / 640, k = r % 640;
            if (k < HID && n < EMBD) v = W2[(size_t)l * HID * EMBD + k * EMBD + n];
        } else if (i < 2150400) {
            int r = i - 2048000;
            int n = r / 320, k = r % 320;
            if (k < EMBD && n < EMBD) v = Wp1[k * EMBD + n];
        } else {
            int r = i - 2150400;
            int n = r / 320, k = r % 320;
            if (k < EMBD && n < EMBD) v = Wp2[k * EMBD + n];
        }
        g_wbuf[i] = __float2half_rn(v);
    }
    // table rows @ W1 -> W1 buffer cols 300..312
    for (int t = gid; t < 5 * 640 * 13; t += stride) {
        int l = t / (640 * 13), r = t % (640 * 13);
        int n = r / 13, j = r % 13;
        float v = 0.f;
        if (n < HID && (j < 7 || l == 0)) {
            const float* R1;
            const float* R2 = nullptr;
            if (j < 3) R1 = ee1 + (l * 6 + j) * EMBD;
            else if (j < 6) R1 = ee2 + (l * 3 + (j - 3)) * EMBD;
            else if (j == 6) { R1 = ee1 + (l * 6 + 4) * EMBD; R2 = ee2 + (l * 3) * EMBD; }
            else if (j < 10) R1 = ae1 + (j - 7) * EMBD;
            else R1 = ae2 + (j - 10) * EMBD;
            const float* Wc = W1 + (size_t)l * EMBD * HID + n;
            float acc = 0.f;
            if (R2) {
                for (int k = 0; k < EMBD; k++)
                    acc = fmaf(R1[k] + R2[k], Wc[(size_t)k * HID], acc);
            } else {
                for (int k = 0; k < EMBD; k++)
                    acc = fmaf(R1[k], Wc[(size_t)k * HID], acc);
            }
            v = acc;
        }
        g_wbuf[WOFF_W1(l) + (size_t)n * 320 + 300 + j] = __float2half_rn(v);
    }
    for (int i = gid; i < 2 * NNODES * 16; i += stride) g_cnt[i] = 0;
    for (int i = gid; i <= M2; i += stride) g_cursor[i] = 0;
    if (gid < 2 * EMBD) { g_bnsum[gid] = 0.f; g_bnss[gid] = 0.f; }
}

__global__ void convert_split_kernel(const float* __restrict__ src, int n,
                                     __half* __restrict__ hi,
                                     __half* __restrict__ lo) {
    int idx = blockIdx.x * blockDim.x + threadIdx.x;
    if (idx >= n) return;
    float v = src[idx];
    __half h = __float2half_rn(v);
    hi[idx] = h;
    lo[idx] = __float2half_rn(v - __half2float(h));
}

__global__ void convert_h_kernel(const float* __restrict__ src, int n,
                                 __half* __restrict__ hi) {
    int idx = blockIdx.x * blockDim.x + threadIdx.x;
    if (idx >= n) return;
    hi[idx] = __float2half_rn(src[idx]);
}

// ---------------- graph structure (virtual rows: enc*MPAD + n) -------------
__global__ void edge_count_kernel(const int* __restrict__ ei,
                                  const int* __restrict__ ea,
                                  const int* __restrict__ x,
                                  int rowbase, int qbase) {
    int e = blockIdx.x * blockDim.x + threadIdx.x;
    if (e >= NEDGES) return;
    int dst = ei[NEDGES + e];
    int src = ei[e];
    atomicAdd(&g_cursor[rowbase + dst], 1);
    int* cnt = g_cnt + (size_t)(qbase + dst) * 16;
    atomicAdd(&cnt[ea[2 * e] & 3], 1);
    atomicAdd(&cnt[4 + (ea[2 * e + 1] & 3)], 1);
    atomicAdd(&cnt[8 + (x[2 * src] & 3)], 1);
    atomicAdd(&cnt[12 + (x[2 * src + 1] & 3)], 1);
}

// coefficient cols + zero feature cols of A, both encoders
__global__ void coeff_zero_kernel(const int* __restrict__ x0,
                                  const int* __restrict__ x1) {
    int idx = blockIdx.x * blockDim.x + threadIdx.x;
    if (idx >= 2 * NNODES * 80) return;
    int nc = idx / 80, c4 = idx % 80;
    int enc = nc >= NNODES;
    int n = nc - enc * NNODES;
    const int* x = enc ? x1 : x0;
    size_t row = (size_t)(enc ? MPAD + n : n);
    size_t o = row * LDH + c4 * 4;
    if (c4 < 75) {
        *reinterpret_cast<uint2*>(&g_ahi[o]) = make_uint2(0u, 0u);
        return;
    }
    const int* cnt = g_cnt + (size_t)(enc * NNODES + n) * 16;
    float v0 = 0.f, v1 = 0.f, v2 = 0.f, v3 = 0.f;
    if (c4 == 75) {
        v0 = (float)cnt[0]; v1 = (float)cnt[1];
        v2 = (float)cnt[2]; v3 = (float)cnt[4];
    } else if (c4 == 76) {
        int xa = x[2 * n] & 3;
        v0 = (float)cnt[5]; v1 = (float)cnt[6];
        v2 = 1.f; v3 = (float)cnt[8] + (xa == 0 ? 1.f : 0.f);
    } else if (c4 == 77) {
        int xa = x[2 * n] & 3, xb = x[2 * n + 1] & 3;
        v0 = (float)cnt[9] + (xa == 1 ? 1.f : 0.f);
        v1 = (float)cnt[10] + (xa == 2 ? 1.f : 0.f);
        v2 = (float)cnt[12] + (xb == 0 ? 1.f : 0.f);
        v3 = (float)cnt[13] + (xb == 1 ? 1.f : 0.f);
    } else if (c4 == 78) {
        int xb = x[2 * n + 1] & 3;
        v0 = (float)cnt[14] + (xb == 2 ? 1.f : 0.f);
    }
    __half2 a = __floats2half2_rn(v0, v1);
    __half2 b = __floats2half2_rn(v2, v3);
    *reinterpret_cast<uint2*>(&g_ahi[o]) =
        make_uint2(*reinterpret_cast<uint32_t*>(&a),
                   *reinterpret_cast<uint32_t*>(&b));
}

__global__ void scan_blocks_kernel() {
    __shared__ int s[1024];
    int tid = threadIdx.x;
    int gid = blockIdx.x * 1024 + tid;
    int v = (gid <= M2) ? g_cursor[gid] : 0;
    s[tid] = v;
    __syncthreads();
    for (int off = 1; off < 1024; off <<= 1) {
        int t = (tid >= off) ? s[tid - off] : 0;
        __syncthreads();
        s[tid] += t;
        __syncthreads();
    }
    if (gid <= M2) g_rowptr[gid] = s[tid] - v;
    if (tid == 1023) g_bsums[blockIdx.x] = s[1023];
}

__global__ void scan_add_kernel() {
    __shared__ int sbase;
    if (threadIdx.x == 0) {
        int acc = 0;
        for (int i = 0; i < (int)blockIdx.x; i++) acc += g_bsums[i];
        sbase = acc;
    }
    __syncthreads();
    int gid = blockIdx.x * 1024 + threadIdx.x;
    if (gid <= M2) {
        int v = g_rowptr[gid] + sbase;
        g_rowptr[gid] = v;
        g_cursor[gid] = v;
    }
}

__global__ void fill_csr_kernel(const int* __restrict__ ei, int rowbase) {
    int e = blockIdx.x * blockDim.x + threadIdx.x;
    if (e >= NEDGES) return;
    int dst = ei[NEDGES + e];
    int pos = atomicAdd(&g_cursor[rowbase + dst], 1);
    g_colidx[pos] = rowbase + ei[e];
}

// ---------------- layers 1..4 agg: fp16 gather, 8 cols/thread, both encs ----
__global__ void agg_kernel() {
    int idx = blockIdx.x * blockDim.x + threadIdx.x;
    if (idx >= 2 * NNODES * C8) return;
    int nc = idx / C8, c8 = idx % C8;
    int enc = nc >= NNODES;
    size_t row = (size_t)nc + (size_t)enc * (MPAD - NNODES);
    int c = c8 * 8;
    const float* bsc = g_bnscale + enc * 320;
    const float* bsh = g_bnshift + enc * 320;
    int rs = g_rowptr[row], re = g_rowptr[row + 1];
    if (c8 < 37) {
        float4 sc0 = ld4(bsc + c), sh0 = ld4(bsh + c);
        float4 sc1 = ld4(bsc + c + 4), sh1 = ld4(bsh + c + 4);
        float a[8];
#pragma unroll
        for (int k = 0; k < 8; k++) a[k] = 0.f;
        float a2[8];
#pragma unroll
        for (int k = 0; k < 8; k++) a2[k] = 0.f;
        auto addrow = [&](const __half* r, float* acc) {
            uint4 u = *reinterpret_cast<const uint4*>(r);
            float2 f0 = __half22float2(*reinterpret_cast<__half2*>(&u.x));
            float2 f1 = __half22float2(*reinterpret_cast<__half2*>(&u.y));
            float2 f2 = __half22float2(*reinterpret_cast<__half2*>(&u.z));
            float2 f3 = __half22float2(*reinterpret_cast<__half2*>(&u.w));
            acc[0] += fmaxf(fmaf(f0.x, sc0.x, sh0.x), 0.f);
            acc[1] += fmaxf(fmaf(f0.y, sc0.y, sh0.y), 0.f);
            acc[2] += fmaxf(fmaf(f1.x, sc0.z, sh0.z), 0.f);
            acc[3] += fmaxf(fmaf(f1.y, sc0.w, sh0.w), 0.f);
            acc[4] += fmaxf(fmaf(f2.x, sc1.x, sh1.x), 0.f);
            acc[5] += fmaxf(fmaf(f2.y, sc1.y, sh1.y), 0.f);
            acc[6] += fmaxf(fmaf(f3.x, sc1.z, sh1.z), 0.f);
            acc[7] += fmaxf(fmaf(f3.y, sc1.w, sh1.w), 0.f);
        };
        addrow(g_hh + row * LDH + c, a);
        int i = rs;
        for (; i + 2 <= re; i += 2) {
            int s0 = g_colidx[i], s1 = g_colidx[i + 1];
            addrow(g_hh + (size_t)s0 * LDH + c, a);
            addrow(g_hh + (size_t)s1 * LDH + c, a2);
        }
        if (i < re) addrow(g_hh + (size_t)g_colidx[i] * LDH + c, a);
#pragma unroll
        for (int k = 0; k < 8; k++) a[k] += a2[k];
        __half2 o0 = __floats2half2_rn(a[0], a[1]);
        __half2 o1 = __floats2half2_rn(a[2], a[3]);
        __half2 o2 = __floats2half2_rn(a[4], a[5]);
        __half2 o3 = __floats2half2_rn(a[6], a[7]);
        uint4 out;
        out.x = *reinterpret_cast<uint32_t*>(&o0);
        out.y = *reinterpret_cast<uint32_t*>(&o1);
        out.z = *reinterpret_cast<uint32_t*>(&o2);
        out.w = *reinterpret_cast<uint32_t*>(&o3);
        *reinterpret_cast<uint4*>(&g_ahi[row * LDH + c]) = out;
    } else {
        float4 sc0 = ld4(bsc + c), sh0 = ld4(bsh + c);
        float a[4] = {0.f, 0.f, 0.f, 0.f};
        auto addrow4 = [&](const __half* r) {
            uint2 u = *reinterpret_cast<const uint2*>(r);
            float2 f0 = __half22float2(*reinterpret_cast<__half2*>(&u.x));
            float2 f1 = __half22float2(*reinterpret_cast<__half2*>(&u.y));
            a[0] += fmaxf(fmaf(f0.x, sc0.x, sh0.x), 0.f);
            a[1] += fmaxf(fmaf(f0.y, sc0.y, sh0.y), 0.f);
            a[2] += fmaxf(fmaf(f1.x, sc0.z, sh0.z), 0.f);
            a[3] += fmaxf(fmaf(f1.y, sc0.w, sh0.w), 0.f);
        };
        addrow4(g_hh + row * LDH + c);
        for (int i = rs; i < re; i++)
            addrow4(g_hh + (size_t)g_colidx[i] * LDH + c);
        __half2 o0 = __floats2half2_rn(a[0], a[1]);
        __half2 o1 = __floats2half2_rn(a[2], a[3]);
        uint2 out;
        out.x = *reinterpret_cast<uint32_t*>(&o0);
        out.y = *reinterpret_cast<uint32_t*>(&o1);
        *reinterpret_cast<uint2*>(&g_ahi[row * LDH + c]) = out;
    }
}

// ---------------- stage loader, templated N-tile -----------------------------
template <int TERMS, int NT>
__device__ __forceinline__ void gemm_load_stage(
    uint32_t sbase, int tid, int m0, int n0, int k0,
    const __half* Ahi, const __half* Alo, int lda,
    const __half* Bh, int Kpad, int Npad) {
    constexpr uint32_t SMB = TERMS * 16384;
#pragma unroll
    for (int it = 0; it < 2; it++) {
        int L = it * GTHREADS + tid;
        int row = L >> 3, j = L & 7;
        uint32_t soff = (uint32_t)row * 128 +
                        (((uint32_t)j * 16) ^ (((uint32_t)(row & 7)) << 4));
        size_t aoff = (size_t)(m0 + row) * lda + k0 + j * 8;
        cpasync16(sbase + soff, Ahi + aoff);
        if (TERMS == 2) cpasync16(sbase + 16384 + soff, Alo + aoff);
    }
#pragma unroll
    for (int it = 0; it < NT / 64; it++) {
        int L = it * GTHREADS + tid;
        int row = L >> 3, j = L & 7;
        uint32_t soff = (uint32_t)row * 128 +
                        (((uint32_t)j * 16) ^ (((uint32_t)(row & 7)) << 4));
        int brow = n0 + row;
        brow = brow < Npad ? brow : Npad - 1;
        size_t boff = (size_t)brow * Kpad + k0 + j * 8;
        cpasync16(sbase + SMB + soff, Bh + boff);
    }
    asm volatile("cp.async.commit_group;" ::: "memory");
}

// ---------------- fp16 mma.sync GEMM, tile 128M x NT-N, 3-stage -------------
// 512 threads, warp grid 4m x 4n. SPLITOUT: 0 fp32, 1 fp16 hi+lo, 2 hi only.
// STATS: per-encoder column stats (row half selects bnsum/bnss offset).
template <int RELU, int SPLITOUT, int STATS, int TERMS, int NT>
__global__ void __launch_bounds__(GTHREADS, 1)
mma_gemm(const __half* __restrict__ Ahi, const __half* __restrict__ Alo,
         int lda, int Kpad,
         const __half* __restrict__ Bh, int Npad,
         const float* __restrict__ bias, float scale,
         float* __restrict__ C, __half* __restrict__ Chi,
         __half* __restrict__ Clo, int ldc, int Nreal) {
    extern __shared__ char smem[];
    constexpr int JN = NT / 32;
    constexpr int NQ = NT / 64;
    constexpr uint32_t SMB = TERMS * 16384;
    constexpr uint32_t STG = SMB + NT * 128;
    uint32_t sb = smem_u32(smem);
    int tid = threadIdx.x;
    int m0 = blockIdx.y * 128, n0 = blockIdx.x * NT;
    int nchunks = Kpad >> 6;

    gemm_load_stage<TERMS, NT>(sb, tid, m0, n0, 0, Ahi, Alo, lda, Bh, Kpad, Npad);
    gemm_load_stage<TERMS, NT>(sb + STG, tid, m0, n0, 64, Ahi, Alo, lda, Bh, Kpad, Npad);

    int lane = tid & 31, wid = tid >> 5;
    int wm = wid & 3, wn = wid >> 2;

    float acc[2][JN][4];
#pragma unroll
    for (int i = 0; i < 2; i++)
#pragma unroll
        for (int j = 0; j < JN; j++)
#pragma unroll
            for (int r = 0; r < 4; r++) acc[i][j][r] = 0.f;

    uint32_t mask = ((uint32_t)(lane & 7)) << 4;
    uint32_t a_row_off[2];
#pragma unroll
    for (int i = 0; i < 2; i++)
        a_row_off[i] = (uint32_t)(wm * 32 + i * 16 + (lane & 15)) * 128;
    uint32_t a_kb_base = (uint32_t)((lane >> 4) * 16);
    int g = lane >> 3;
    uint32_t b_row_base = (uint32_t)(wn * (NT / 4) + (g >> 1) * 8 + (lane & 7));
    uint32_t b_kb_base = (uint32_t)((g & 1) * 16);

    int slot = 0;
    for (int ch = 0; ch < nchunks; ch++) {
        asm volatile("cp.async.wait_group 1;" ::: "memory");
        __syncthreads();
        if (ch + 2 < nchunks) {
            int ns = slot + 2;
            if (ns >= 3) ns -= 3;
            gemm_load_stage<TERMS, NT>(sb + (uint32_t)ns * STG, tid, m0, n0,
                                       (ch + 2) * 64, Ahi, Alo, lda, Bh, Kpad, Npad);
        } else {
            asm volatile("cp.async.commit_group;" ::: "memory");
        }
        uint32_t st = sb + (uint32_t)slot * STG;
#pragma unroll
        for (int s = 0; s < 4; s++) {
            uint32_t akb = (a_kb_base + s * 32) ^ mask;
            uint32_t bkb = (b_kb_base + s * 32) ^ mask;
            uint32_t ah[2][4], al[2][4];
#pragma unroll
            for (int i = 0; i < 2; i++) {
                LDSM_X4(ah[i][0], ah[i][1], ah[i][2], ah[i][3],
                        st + a_row_off[i] + akb);
                if (TERMS == 2)
                    LDSM_X4(al[i][0], al[i][1], al[i][2], al[i][3],
                            st + 16384 + a_row_off[i] + akb);
            }
#pragma unroll
            for (int q = 0; q < NQ; q++) {
                uint32_t broff = (b_row_base + q * 16) * 128;
                uint32_t bh[4];
                LDSM_X4(bh[0], bh[1], bh[2], bh[3], st + SMB + broff + bkb);
#pragma unroll
                for (int i = 0; i < 2; i++) {
                    MMA16816(acc[i][2 * q], ah[i], bh[0], bh[1]);
                    if (TERMS == 2)
                        MMA16816(acc[i][2 * q], al[i], bh[0], bh[1]);
                    MMA16816(acc[i][2 * q + 1], ah[i], bh[2], bh[3]);
                    if (TERMS == 2)
                        MMA16816(acc[i][2 * q + 1], al[i], bh[2], bh[3]);
                }
            }
        }
        if (++slot == 3) slot = 0;
    }

    // ---- epilogue (+ per-encoder column stats) ----
    int encoff = 0;
    if (STATS) encoff = (m0 >= MPAD) ? EMBD : 0;
#pragma unroll
    for (int j = 0; j < JN; j++) {
        int col = n0 + wn * (NT / 4) + j * 8 + (lane & 3) * 2;
        float b0 = 0.f, b1 = 0.f;
        if (bias != nullptr) {
            b0 = (col < Nreal) ? bias[col] : 0.f;
            b1 = (col + 1 < Nreal) ? bias[col + 1] : 0.f;
        }
        float s0 = 0.f, s1 = 0.f, q0 = 0.f, q1 = 0.f;
#pragma unroll
        for (int i = 0; i < 2; i++) {
            int r0 = m0 + wm * 32 + i * 16 + (lane >> 2);
            float v00 = (col < Nreal) ? (acc[i][j][0] + b0) * scale : 0.f;
            float v01 = (col + 1 < Nreal) ? (acc[i][j][1] + b1) * scale : 0.f;
            float v10 = (col < Nreal) ? (acc[i][j][2] + b0) * scale : 0.f;
            float v11 = (col + 1 < Nreal) ? (acc[i][j][3] + b1) * scale : 0.f;
            if (RELU) {
                v00 = fmaxf(v00, 0.f); v01 = fmaxf(v01, 0.f);
                v10 = fmaxf(v10, 0.f); v11 = fmaxf(v11, 0.f);
            }
            if (STATS) {
                int rr = (r0 >= MPAD) ? r0 - MPAD : r0;
                bool ok0 = (rr < NNODES), ok1 = (rr + 8 < NNODES);
                s0 += (ok0 ? v00 : 0.f) + (ok1 ? v10 : 0.f);
                s1 += (ok0 ? v01 : 0.f) + (ok1 ? v11 : 0.f);
                q0 += (ok0 ? v00 * v00 : 0.f) + (ok1 ? v10 * v10 : 0.f);
                q1 += (ok0 ? v01 * v01 : 0.f) + (ok1 ? v11 * v11 : 0.f);
            }
            if (col < ldc) {
                if (SPLITOUT >= 1) {
                    __half h00 = __float2half_rn(v00);
                    __half h01 = __float2half_rn(v01);
                    __half h10 = __float2half_rn(v10);
                    __half h11 = __float2half_rn(v11);
                    *reinterpret_cast<__half2*>(Chi + (size_t)r0 * ldc + col) =
                        __halves2half2(h00, h01);
                    *reinterpret_cast<__half2*>(Chi + (size_t)(r0 + 8) * ldc + col) =
                        __halves2half2(h10, h11);
                    if (SPLITOUT == 1) {
                        __half2 ll0 = __halves2half2(
                            __float2half_rn(v00 - __half2float(h00)),
                            __float2half_rn(v01 - __half2float(h01)));
                        __half2 ll1 = __halves2half2(
                            __float2half_rn(v10 - __half2float(h10)),
                            __float2half_rn(v11 - __half2float(h11)));
                        *reinterpret_cast<__half2*>(Clo + (size_t)r0 * ldc + col) = ll0;
                        *reinterpret_cast<__half2*>(Clo + (size_t)(r0 + 8) * ldc + col) = ll1;
                    }
                } else {
                    *reinterpret_cast<float2*>(C + (size_t)r0 * ldc + col) =
                        make_float2(v00, v01);
                    *reinterpret_cast<float2*>(C + (size_t)(r0 + 8) * ldc + col) =
                        make_float2(v10, v11);
                }
            }
        }
        if (STATS) {
#pragma unroll
            for (int o = 16; o >= 4; o >>= 1) {
                s0 += __shfl_down_sync(0xffffffffu, s0, o);
                s1 += __shfl_down_sync(0xffffffffu, s1, o);
                q0 += __shfl_down_sync(0xffffffffu, q0, o);
                q1 += __shfl_down_sync(0xffffffffu, q1, o);
            }
            if (lane < 4 && col < Nreal) {
                atomicAdd(&g_bnsum[encoff + col], s0);
                atomicAdd(&g_bnsum[encoff + col + 1], s1);
                atomicAdd(&g_bnss[encoff + col], q0);
                atomicAdd(&g_bnss[encoff + col + 1], q1);
            }
        }
    }
}

// ---------------- BatchNorm finalize, both encoders (self-resets) -----------
__global__ void bn_finalize_kernel(const float* __restrict__ gamma,
                                   const float* __restrict__ beta) {
    int enc = blockIdx.x;
    int c = threadIdx.x;
    if (c >= EMBD) return;
    float sum = g_bnsum[enc * EMBD + c], ss = g_bnss[enc * EMBD + c];
    float mean = sum * (1.0f / NNODES);
    float var = ss * (1.0f / NNODES) - mean * mean;
    float rs = rsqrtf(var + 1e-5f);
    float s = rs * gamma[c];
    g_bnscale[enc * 320 + c] = s;
    g_bnshift[enc * 320 + c] = beta[c] - mean * s;
    g_bnsum[enc * EMBD + c] = 0.f;
    g_bnss[enc * EMBD + c] = 0.f;
}

// ---------------- segment pooling, both encoders ----------------------------
__global__ void pool_seg_kernel(const int* __restrict__ bi0,
                                const int* __restrict__ bi1) {
    __shared__ int s_lo, s_hi;
    int gg = blockIdx.x;
    int enc = gg >= NGRAPHS;
    int g = gg - enc * NGRAPHS;
    const int* bi = enc ? bi1 : bi0;
    if (threadIdx.x == 0) {
        int lo = 0, hi = NNODES;
        while (lo < hi) { int m = (lo + hi) >> 1; if (bi[m] < g) lo = m + 1; else hi = m; }
        s_lo = lo;
        int lo2 = lo, hi2 = NNODES;
        while (lo2 < hi2) { int m = (lo2 + hi2) >> 1; if (bi[m] < g + 1) lo2 = m + 1; else hi2 = m; }
        s_hi = lo2;
    }
    __syncthreads();
    int lo = s_lo, hi = s_hi;
    float inv = 1.0f / fmaxf((float)(hi - lo), 1.0f);
    size_t rbase = (size_t)enc * MPAD;
    int c0 = threadIdx.x, c1 = c0 + 128, c2 = c0 + 256;
    float a0 = 0.f, a1 = 0.f, a2 = 0.f;
    for (int r = lo; r < hi; r++) {
        const __half* row = g_hh + (rbase + r) * LDH;
        a0 += __half2float(row[c0]);
        a1 += __half2float(row[c1]);
        if (c2 < EMBD) a2 += __half2float(row[c2]);
    }
    const float* bsc = g_bnscale + enc * 320;
    const float* bsh = g_bnshift + enc * 320;
    float* dst = g_pool + (size_t)gg * LDH;
    dst[c0] = fmaf(a0 * inv, bsc[c0], bsh[c0]);
    dst[c1] = fmaf(a1 * inv, bsc[c1], bsh[c1]);
    if (c2 < EMBD) dst[c2] = fmaf(a2 * inv, bsc[c2], bsh[c2]);
    else if (c2 < LDH) dst[c2] = 0.f;
}

// ---------------- L2 row normalize ----------------
__global__ void normalize_kernel(float* __restrict__ f) {
    __shared__ float red[4];
    size_t r = blockIdx.x;
    float* row = f + r * LDH;
    float ss = 0.f;
    for (int c = threadIdx.x; c < EMBD; c += 128) {
        float v = row[c];
        ss += v * v;
    }
    for (int o = 16; o; o >>= 1) ss += __shfl_down_sync(0xffffffffu, ss, o);
    if ((threadIdx.x & 31) == 0) red[threadIdx.x >> 5] = ss;
    __syncthreads();
    if (threadIdx.x == 0) red[0] = rsqrtf(red[0] + red[1] + red[2] + red[3]);
    __syncthreads();
    float s = red[0];
    for (int c = threadIdx.x; c < EMBD; c += 128) row[c] *= s;
}

__global__ void labels_kernel(float* __restrict__ out, int extra) {
    int i = blockIdx.x * blockDim.x + threadIdx.x;
    if (i < extra) out[i] = (float)i;
}

// ---------------- host orchestration ----------------
extern "C" void kernel_launch(void* const* d_in, const int* in_sizes, int n_in,
                              void* d_out, int out_size) {
    const float* ae1 = (const float*)d_in[8];
    const float* ae2 = (const float*)d_in[9];
    const float* ee1 = (const float*)d_in[10];
    const float* ee2 = (const float*)d_in[11];
    const float* W1 = (const float*)d_in[12];
    const float* bm1 = (const float*)d_in[13];
    const float* W2 = (const float*)d_in[14];
    const float* bm2 = (const float*)d_in[15];
    const float* gamma = (const float*)d_in[16];
    const float* beta = (const float*)d_in[17];
    const float* bp1 = (const float*)d_in[19];
    const float* bp2 = (const float*)d_in[21];

    float *pool, *feat;
    __half *ahi, *hh, *thi, *phi, *plo, *qlo, *wbuf;
    cudaGetSymbolAddress((void**)&pool, g_pool);
    cudaGetSymbolAddress((void**)&feat, g_feat);
    cudaGetSymbolAddress((void**)&ahi, g_ahi);
    cudaGetSymbolAddress((void**)&hh, g_hh);
    cudaGetSymbolAddress((void**)&thi, g_thi);
    cudaGetSymbolAddress((void**)&phi, g_phi);
    cudaGetSymbolAddress((void**)&plo, g_plo);
    cudaGetSymbolAddress((void**)&qlo, g_qlo);
    cudaGetSymbolAddress((void**)&wbuf, g_wbuf);

    const int SM_G1 = 3 * (16384 + 320 * 128);   // TERMS=1, NT=320
    const int SM_P = 3 * (32768 + 320 * 128);    // TERMS=2, NT=320
    const int SM_L = 3 * (32768 + 256 * 128);    // TERMS=2, NT=256
    cudaFuncSetAttribute(mma_gemm<1, 2, 0, 1, 320>,
                         cudaFuncAttributeMaxDynamicSharedMemorySize, SM_G1);
    cudaFuncSetAttribute(mma_gemm<0, 2, 1, 1, 320>,
                         cudaFuncAttributeMaxDynamicSharedMemorySize, SM_G1);
    cudaFuncSetAttribute(mma_gemm<1, 1, 0, 2, 320>,
                         cudaFuncAttributeMaxDynamicSharedMemorySize, SM_P);
    cudaFuncSetAttribute(mma_gemm<0, 0, 0, 2, 320>,
                         cudaFuncAttributeMaxDynamicSharedMemorySize, SM_P);
    cudaFuncSetAttribute(mma_gemm<0, 0, 0, 2, 256>,
                         cudaFuncAttributeMaxDynamicSharedMemorySize, SM_L);

    const int GE = (NEDGES + 255) / 256;
    const int GC = (2 * NNODES * 80 + 255) / 256;
    const int GA = (2 * NNODES * C8 + 255) / 256;
    const int GP2 = (2 * NGRAPHS * LDH + 255) / 256;
    const int GP1 = (NGRAPHS * LDH + 255) / 256;

    const int* x0 = (const int*)d_in[0];
    const int* ei0 = (const int*)d_in[1];
    const int* ea0 = (const int*)d_in[2];
    const int* bi0 = (const int*)d_in[3];
    const int* x1 = (const int*)d_in[4];
    const int* ei1 = (const int*)d_in[5];
    const int* ea1 = (const int*)d_in[6];
    const int* bi1 = (const int*)d_in[7];

    // init: weights + table products + zero all graph/bn buffers
    convert_all_kernel<<<2048, 256>>>(W1, W2, (const float*)d_in[18],
                                      (const float*)d_in[20],
                                      ae1, ae2, ee1, ee2);
    // counts for both encoders
    edge_count_kernel<<<GE, 256>>>(ei0, ea0, x0, 0, 0);
    edge_count_kernel<<<GE, 256>>>(ei1, ea1, x1, MPAD, NNODES);
    coeff_zero_kernel<<<GC, 256>>>(x0, x1);

    for (int l = 0; l < NLAYERS; l++) {
        if (l > 0) agg_kernel<<<GA, 256>>>();

        // GEMM1: A @ W1ext -> thi, relu. M = 2*MPAD, N=640 exact.
        mma_gemm<1, 2, 0, 1, 320><<<dim3(2, 2 * MTOT), GTHREADS, SM_G1>>>(
            ahi, nullptr, 320, 320, wbuf + WOFF_W1(l), 640, bm1 + l * HID,
            1.0f, nullptr, thi, nullptr, LDT, HID);

        if (l == 0) {  // combined CSR build, ready before agg(l=1)
            scan_blocks_kernel<<<NB2, 1024>>>();
            scan_add_kernel<<<NB2, 1024>>>();
            fill_csr_kernel<<<GE, 256>>>(ei0, 0);
            fill_csr_kernel<<<GE, 256>>>(ei1, MPAD);
        }

        // GEMM2: thi @ W2 -> h fp16 + per-encoder stats. N=320 exact.
        mma_gemm<0, 2, 1, 1, 320><<<dim3(1, 2 * MTOT), GTHREADS, SM_G1>>>(
            thi, nullptr, LDT, 640, wbuf + WOFF_W2(l), 320, bm2 + l * EMBD,
            1.0f, nullptr, hh, nullptr, LDH, EMBD);
        bn_finalize_kernel<<<2, 512>>>(gamma + l * EMBD, beta + l * EMBD);
    }

    // segment mean-pool, both encoders
    pool_seg_kernel<<<2 * NGRAPHS, 128>>>(bi0, bi1);

    // projection head, M = 8192 (both encoders)
    convert_split_kernel<<<GP2, 256>>>(pool, 2 * NGRAPHS * LDH, phi, plo);
    mma_gemm<1, 1, 0, 2, 320><<<dim3(1, 64), GTHREADS, SM_P>>>(
        phi, plo, 320, 320, wbuf + WOFF_P1, 320, bp1, 1.0f,
        nullptr, thi, qlo, 320, EMBD);
    mma_gemm<0, 0, 0, 2, 320><<<dim3(1, 64), GTHREADS, SM_P>>>(
        thi, qlo, 320, 320, wbuf + WOFF_P2, 320, bp2, 1.0f,
        feat, nullptr, nullptr, LDH, EMBD);

    normalize_kernel<<<2 * NGRAPHS, 128>>>(feat);

    // logits = 25 * f0 @ f1^T : f0 split (A, 2-term), f1 single fp16 (B)
    convert_split_kernel<<<GP1, 256>>>(feat, NGRAPHS * LDH, phi, plo);
    convert_h_kernel<<<GP1, 256>>>(feat + (size_t)NGRAPHS * LDH,
                                   NGRAPHS * LDH, qlo);
    mma_gemm<0, 0, 0, 2, 256><<<dim3(NGRAPHS / 256, NGRAPHS / 128), GTHREADS, SM_L>>>(
        phi, plo, 320, 320, qlo, NGRAPHS,
        nullptr, 25.0f, (float*)d_out, nullptr, nullptr, NGRAPHS, NGRAPHS);

    long long logits_elems = (long long)NGRAPHS * NGRAPHS;
    int extra = (int)((long long)out_size - logits_elems);
    if (extra > 0)
        labels_kernel<<<(extra + 255) / 256, 256>>>(
            (float*)d_out + logits_elems, extra);
}

// round 17
// speedup vs baseline: 1.1008x; 1.0447x over previous
#include <cuda_runtime.h>
#include <cuda_fp16.h>
#include <math.h>
#include <stdint.h>

#define NNODES 200000
#define NEDGES 440000
#define NGRAPHS 4096
#define EMBD 300
#define HID 600
#define C8 38
#define NLAYERS 5

#define LDH 320
#define LDT 640
#define MPAD 200064             // 1563 * 128
#define MTOT 1563
#define M2 (2 * MPAD)
#define NB2 ((M2 + 1 + 1023) / 1024)

// weight buffer offsets (halves)
#define WOFF_W1(l) ((size_t)(l) * 204800)
#define WOFF_W2(l) (1024000 + (size_t)(l) * 204800)
#define WOFF_P1 2048000
#define WOFF_P2 2150400
#define WBUF_SZ 2252800

// ---------------- scratch (both encoders batched) ----------------
__device__ __align__(16) __half g_ahi[(size_t)M2 * LDH];
__device__ __align__(16) __half g_hh[(size_t)M2 * LDH];
__device__ __align__(16) __half g_thi[(size_t)M2 * LDT];
__device__ __align__(16) __half g_a0[(size_t)M2 * 64 + 256];  // layer-0 compact A
__device__ __align__(16) __half g_w1l0[640 * 64 + 128];       // layer-0 compact W1
__device__ __align__(16) __half g_phi[2 * NGRAPHS * LDH];
__device__ __align__(16) __half g_plo[2 * NGRAPHS * LDH];
__device__ __align__(16) __half g_qlo[2 * NGRAPHS * LDH];
__device__ __align__(16) __half g_wbuf[WBUF_SZ];
__device__ int   g_cnt[2 * NNODES * 16];
__device__ int   g_rowptr[M2 + 2];
__device__ int   g_cursor[M2 + 2];
__device__ int   g_colidx[2 * NEDGES];
__device__ int   g_bsums[512];
__device__ float g_bnsum[2 * EMBD];
__device__ float g_bnss[2 * EMBD];
__device__ float g_bnscale[2 * 320];
__device__ float g_bnshift[2 * 320];
__device__ float g_pool[2 * NGRAPHS * LDH];
__device__ float g_feat[2 * NGRAPHS * LDH];

// ---------------- helpers ----------------
__device__ __forceinline__ float4 ld4(const float* p) {
    return *reinterpret_cast<const float4*>(p);
}
__device__ __forceinline__ uint32_t smem_u32(const void* p) {
    uint32_t a;
    asm("{ .reg .u64 t; cvta.to.shared.u64 t, %1; cvt.u32.u64 %0, t; }"
        : "=r"(a) : "l"(p));
    return a;
}
__device__ __forceinline__ void cpasync16(uint32_t dst, const void* src) {
    asm volatile("cp.async.cg.shared.global [%0], [%1], 16;"
                 :: "r"(dst), "l"(src));
}

#define LDSM_X4(r0, r1, r2, r3, addr) \
    asm volatile("ldmatrix.sync.aligned.m8n8.x4.shared.b16 {%0,%1,%2,%3}, [%4];" \
                 : "=r"(r0), "=r"(r1), "=r"(r2), "=r"(r3) : "r"(addr))

#define MMA16816(c, a, b0, b1) \
    asm volatile("mma.sync.aligned.m16n8k16.row.col.f32.f16.f16.f32 " \
                 "{%0,%1,%2,%3}, {%4,%5,%6,%7}, {%8,%9}, {%0,%1,%2,%3};" \
                 : "+f"((c)[0]), "+f"((c)[1]), "+f"((c)[2]), "+f"((c)[3]) \
                 : "r"((a)[0]), "r"((a)[1]), "r"((a)[2]), "r"((a)[3]), \
                   "r"(b0), "r"(b1))

#define GTHREADS 512

// ---------------- fused init: weights, table-products, zeroing --------------
__global__ void convert_all_kernel(const float* __restrict__ W1,
                                   const float* __restrict__ W2,
                                   const float* __restrict__ Wp1,
                                   const float* __restrict__ Wp2,
                                   const float* __restrict__ ae1,
                                   const float* __restrict__ ae2,
                                   const float* __restrict__ ee1,
                                   const float* __restrict__ ee2) {
    int gid = blockIdx.x * blockDim.x + threadIdx.x;
    int stride = gridDim.x * blockDim.x;
    for (int i = gid; i < WBUF_SZ; i += stride) {
        float v = 0.f;
        if (i < 1024000) {
            int l = i / 204800, r = i % 204800;
            int n = r / 320, k = r % 320;
            if (k >= 300 && k < 313) continue;  // phase 2 owns these
            if (k < EMBD && n < HID) v = W1[(size_t)l * EMBD * HID + k * HID + n];
        } else if (i < 2048000) {
            int j = i - 1024000;
            int l = j / 204800, r = j % 204800;
            int n = r / 640, k = r % 640;
            if (k < HID && n < EMBD) v = W2[(size_t)l * HID * EMBD + k * EMBD + n];
        } else if (i < 2150400) {
            int r = i - 2048000;
            int n = r / 320, k = r % 320;
            if (k < EMBD && n < EMBD) v = Wp1[k * EMBD + n];
        } else {
            int r = i - 2150400;
            int n = r / 320, k = r % 320;
            if (k < EMBD && n < EMBD) v = Wp2[k * EMBD + n];
        }
        g_wbuf[i] = __float2half_rn(v);
    }
    // zero layer-0 compact W1 cols 13..63 (cols 0..12 written in phase 2)
    for (int i = gid; i < 640 * 64 + 128; i += stride) {
        int k = i & 63;
        if (k >= 13 || i >= 640 * 64) g_w1l0[i] = __ushort_as_half(0);
    }
    // table rows @ W1 -> W1 buffer cols 300..312 (+ layer-0 compact rows)
    for (int t = gid; t < 5 * 640 * 13; t += stride) {
        int l = t / (640 * 13), r = t % (640 * 13);
        int n = r / 13, j = r % 13;
        float v = 0.f;
        if (n < HID && (j < 7 || l == 0)) {
            const float* R1;
            const float* R2 = nullptr;
            if (j < 3) R1 = ee1 + (l * 6 + j) * EMBD;
            else if (j < 6) R1 = ee2 + (l * 3 + (j - 3)) * EMBD;
            else if (j == 6) { R1 = ee1 + (l * 6 + 4) * EMBD; R2 = ee2 + (l * 3) * EMBD; }
            else if (j < 10) R1 = ae1 + (j - 7) * EMBD;
            else R1 = ae2 + (j - 10) * EMBD;
            const float* Wc = W1 + (size_t)l * EMBD * HID + n;
            float acc = 0.f;
            if (R2) {
                for (int k = 0; k < EMBD; k++)
                    acc = fmaf(R1[k] + R2[k], Wc[(size_t)k * HID], acc);
            } else {
                for (int k = 0; k < EMBD; k++)
                    acc = fmaf(R1[k], Wc[(size_t)k * HID], acc);
            }
            v = acc;
        }
        __half hv = __float2half_rn(v);
        g_wbuf[WOFF_W1(l) + (size_t)n * 320 + 300 + j] = hv;
        if (l == 0) g_w1l0[n * 64 + j] = hv;
    }
    for (int i = gid; i < 2 * NNODES * 16; i += stride) g_cnt[i] = 0;
    for (int i = gid; i <= M2; i += stride) g_cursor[i] = 0;
    if (gid < 2 * EMBD) { g_bnsum[gid] = 0.f; g_bnss[gid] = 0.f; }
}

__global__ void convert_split_kernel(const float* __restrict__ src, int n,
                                     __half* __restrict__ hi,
                                     __half* __restrict__ lo) {
    int idx = blockIdx.x * blockDim.x + threadIdx.x;
    if (idx >= n) return;
    float v = src[idx];
    __half h = __float2half_rn(v);
    hi[idx] = h;
    lo[idx] = __float2half_rn(v - __half2float(h));
}

__global__ void convert_h_kernel(const float* __restrict__ src, int n,
                                 __half* __restrict__ hi) {
    int idx = blockIdx.x * blockDim.x + threadIdx.x;
    if (idx >= n) return;
    hi[idx] = __float2half_rn(src[idx]);
}

// ---------------- graph structure (virtual rows: enc*MPAD + n) -------------
__global__ void edge_count_kernel(const int* __restrict__ ei,
                                  const int* __restrict__ ea,
                                  const int* __restrict__ x,
                                  int rowbase, int qbase) {
    int e = blockIdx.x * blockDim.x + threadIdx.x;
    if (e >= NEDGES) return;
    int dst = ei[NEDGES + e];
    int src = ei[e];
    atomicAdd(&g_cursor[rowbase + dst], 1);
    int* cnt = g_cnt + (size_t)(qbase + dst) * 16;
    atomicAdd(&cnt[ea[2 * e] & 3], 1);
    atomicAdd(&cnt[4 + (ea[2 * e + 1] & 3)], 1);
    atomicAdd(&cnt[8 + (x[2 * src] & 3)], 1);
    atomicAdd(&cnt[12 + (x[2 * src + 1] & 3)], 1);
}

// coefficients -> g_a0 cols 0..15 (uint4 ok) and g_ahi cols 300..315 (uint2,
// since 300 halves = 600 B is only 8-byte aligned). Rest zero-by-init.
__global__ void coeff_kernel(const int* __restrict__ x0,
                             const int* __restrict__ x1) {
    int nc = blockIdx.x * blockDim.x + threadIdx.x;
    if (nc >= 2 * NNODES) return;
    int enc = nc >= NNODES;
    int n = nc - enc * NNODES;
    const int* x = enc ? x1 : x0;
    size_t row = (size_t)(enc ? MPAD + n : n);
    const int* cnt = g_cnt + (size_t)(enc * NNODES + n) * 16;
    int xa = x[2 * n] & 3, xb = x[2 * n + 1] & 3;
    float j0 = (float)cnt[0], j1 = (float)cnt[1], j2 = (float)cnt[2];
    float j3 = (float)cnt[4], j4 = (float)cnt[5], j5 = (float)cnt[6];
    float j6 = 1.f;
    float j7 = (float)cnt[8] + (xa == 0 ? 1.f : 0.f);
    float j8 = (float)cnt[9] + (xa == 1 ? 1.f : 0.f);
    float j9 = (float)cnt[10] + (xa == 2 ? 1.f : 0.f);
    float j10 = (float)cnt[12] + (xb == 0 ? 1.f : 0.f);
    float j11 = (float)cnt[13] + (xb == 1 ? 1.f : 0.f);
    float j12 = (float)cnt[14] + (xb == 2 ? 1.f : 0.f);
    __half2 p0 = __floats2half2_rn(j0, j1);
    __half2 p1 = __floats2half2_rn(j2, j3);
    __half2 p2 = __floats2half2_rn(j4, j5);
    __half2 p3 = __floats2half2_rn(j6, j7);
    __half2 p4 = __floats2half2_rn(j8, j9);
    __half2 p5 = __floats2half2_rn(j10, j11);
    __half2 p6 = __floats2half2_rn(j12, 0.f);
    __half2 pz = __floats2half2_rn(0.f, 0.f);
    uint32_t w0 = *reinterpret_cast<uint32_t*>(&p0);
    uint32_t w1 = *reinterpret_cast<uint32_t*>(&p1);
    uint32_t w2 = *reinterpret_cast<uint32_t*>(&p2);
    uint32_t w3 = *reinterpret_cast<uint32_t*>(&p3);
    uint32_t w4 = *reinterpret_cast<uint32_t*>(&p4);
    uint32_t w5 = *reinterpret_cast<uint32_t*>(&p5);
    uint32_t w6 = *reinterpret_cast<uint32_t*>(&p6);
    uint32_t wz = *reinterpret_cast<uint32_t*>(&pz);
    // g_a0: row*64 halves = 128 B aligned -> uint4 ok
    *reinterpret_cast<uint4*>(&g_a0[row * 64]) = make_uint4(w0, w1, w2, w3);
    *reinterpret_cast<uint4*>(&g_a0[row * 64 + 8]) = make_uint4(w4, w5, w6, wz);
    // g_ahi: col 300 -> 600 B offset, 8 B aligned -> uint2 stores
    __half* dst = &g_ahi[row * LDH + 300];
    *reinterpret_cast<uint2*>(dst) = make_uint2(w0, w1);
    *reinterpret_cast<uint2*>(dst + 4) = make_uint2(w2, w3);
    *reinterpret_cast<uint2*>(dst + 8) = make_uint2(w4, w5);
    *reinterpret_cast<uint2*>(dst + 12) = make_uint2(w6, wz);
}

__global__ void scan_blocks_kernel() {
    __shared__ int s[1024];
    int tid = threadIdx.x;
    int gid = blockIdx.x * 1024 + tid;
    int v = (gid <= M2) ? g_cursor[gid] : 0;
    s[tid] = v;
    __syncthreads();
    for (int off = 1; off < 1024; off <<= 1) {
        int t = (tid >= off) ? s[tid - off] : 0;
        __syncthreads();
        s[tid] += t;
        __syncthreads();
    }
    if (gid <= M2) g_rowptr[gid] = s[tid] - v;
    if (tid == 1023) g_bsums[blockIdx.x] = s[1023];
}

__global__ void scan_add_kernel() {
    __shared__ int sbase;
    if (threadIdx.x == 0) {
        int acc = 0;
        for (int i = 0; i < (int)blockIdx.x; i++) acc += g_bsums[i];
        sbase = acc;
    }
    __syncthreads();
    int gid = blockIdx.x * 1024 + threadIdx.x;
    if (gid <= M2) {
        int v = g_rowptr[gid] + sbase;
        g_rowptr[gid] = v;
        g_cursor[gid] = v;
    }
}

__global__ void fill_csr_kernel(const int* __restrict__ ei, int rowbase) {
    int e = blockIdx.x * blockDim.x + threadIdx.x;
    if (e >= NEDGES) return;
    int dst = ei[NEDGES + e];
    int pos = atomicAdd(&g_cursor[rowbase + dst], 1);
    g_colidx[pos] = rowbase + ei[e];
}

// ---------------- layers 1..4 agg: fp16 gather, 8 cols/thread, both encs ----
__global__ void agg_kernel() {
    int idx = blockIdx.x * blockDim.x + threadIdx.x;
    if (idx >= 2 * NNODES * C8) return;
    int nc = idx / C8, c8 = idx % C8;
    int enc = nc >= NNODES;
    size_t row = (size_t)nc + (size_t)enc * (MPAD - NNODES);
    int c = c8 * 8;
    const float* bsc = g_bnscale + enc * 320;
    const float* bsh = g_bnshift + enc * 320;
    int rs = g_rowptr[row], re = g_rowptr[row + 1];
    if (c8 < 37) {
        float4 sc0 = ld4(bsc + c), sh0 = ld4(bsh + c);
        float4 sc1 = ld4(bsc + c + 4), sh1 = ld4(bsh + c + 4);
        float a[8];
#pragma unroll
        for (int k = 0; k < 8; k++) a[k] = 0.f;
        float a2[8];
#pragma unroll
        for (int k = 0; k < 8; k++) a2[k] = 0.f;
        auto addrow = [&](const __half* r, float* acc) {
            uint4 u = *reinterpret_cast<const uint4*>(r);
            float2 f0 = __half22float2(*reinterpret_cast<__half2*>(&u.x));
            float2 f1 = __half22float2(*reinterpret_cast<__half2*>(&u.y));
            float2 f2 = __half22float2(*reinterpret_cast<__half2*>(&u.z));
            float2 f3 = __half22float2(*reinterpret_cast<__half2*>(&u.w));
            acc[0] += fmaxf(fmaf(f0.x, sc0.x, sh0.x), 0.f);
            acc[1] += fmaxf(fmaf(f0.y, sc0.y, sh0.y), 0.f);
            acc[2] += fmaxf(fmaf(f1.x, sc0.z, sh0.z), 0.f);
            acc[3] += fmaxf(fmaf(f1.y, sc0.w, sh0.w), 0.f);
            acc[4] += fmaxf(fmaf(f2.x, sc1.x, sh1.x), 0.f);
            acc[5] += fmaxf(fmaf(f2.y, sc1.y, sh1.y), 0.f);
            acc[6] += fmaxf(fmaf(f3.x, sc1.z, sh1.z), 0.f);
            acc[7] += fmaxf(fmaf(f3.y, sc1.w, sh1.w), 0.f);
        };
        addrow(g_hh + row * LDH + c, a);
        int i = rs;
        for (; i + 2 <= re; i += 2) {
            int s0 = g_colidx[i], s1 = g_colidx[i + 1];
            addrow(g_hh + (size_t)s0 * LDH + c, a);
            addrow(g_hh + (size_t)s1 * LDH + c, a2);
        }
        if (i < re) addrow(g_hh + (size_t)g_colidx[i] * LDH + c, a);
#pragma unroll
        for (int k = 0; k < 8; k++) a[k] += a2[k];
        __half2 o0 = __floats2half2_rn(a[0], a[1]);
        __half2 o1 = __floats2half2_rn(a[2], a[3]);
        __half2 o2 = __floats2half2_rn(a[4], a[5]);
        __half2 o3 = __floats2half2_rn(a[6], a[7]);
        uint4 out;
        out.x = *reinterpret_cast<uint32_t*>(&o0);
        out.y = *reinterpret_cast<uint32_t*>(&o1);
        out.z = *reinterpret_cast<uint32_t*>(&o2);
        out.w = *reinterpret_cast<uint32_t*>(&o3);
        *reinterpret_cast<uint4*>(&g_ahi[row * LDH + c]) = out;
    } else {
        float4 sc0 = ld4(bsc + c), sh0 = ld4(bsh + c);
        float a[4] = {0.f, 0.f, 0.f, 0.f};
        auto addrow4 = [&](const __half* r) {
            uint2 u = *reinterpret_cast<const uint2*>(r);
            float2 f0 = __half22float2(*reinterpret_cast<__half2*>(&u.x));
            float2 f1 = __half22float2(*reinterpret_cast<__half2*>(&u.y));
            a[0] += fmaxf(fmaf(f0.x, sc0.x, sh0.x), 0.f);
            a[1] += fmaxf(fmaf(f0.y, sc0.y, sh0.y), 0.f);
            a[2] += fmaxf(fmaf(f1.x, sc0.z, sh0.z), 0.f);
            a[3] += fmaxf(fmaf(f1.y, sc0.w, sh0.w), 0.f);
        };
        addrow4(g_hh + row * LDH + c);
        for (int i = rs; i < re; i++)
            addrow4(g_hh + (size_t)g_colidx[i] * LDH + c);
        __half2 o0 = __floats2half2_rn(a[0], a[1]);
        __half2 o1 = __floats2half2_rn(a[2], a[3]);
        uint2 out;
        out.x = *reinterpret_cast<uint32_t*>(&o0);
        out.y = *reinterpret_cast<uint32_t*>(&o1);
        *reinterpret_cast<uint2*>(&g_ahi[row * LDH + c]) = out;
    }
}

// ---------------- stage loader, templated N-tile -----------------------------
template <int TERMS, int NT>
__device__ __forceinline__ void gemm_load_stage(
    uint32_t sbase, int tid, int m0, int n0, int k0,
    const __half* Ahi, const __half* Alo, int lda,
    const __half* Bh, int Kpad, int Npad) {
    constexpr uint32_t SMB = TERMS * 16384;
#pragma unroll
    for (int it = 0; it < 2; it++) {
        int L = it * GTHREADS + tid;
        int row = L >> 3, j = L & 7;
        uint32_t soff = (uint32_t)row * 128 +
                        (((uint32_t)j * 16) ^ (((uint32_t)(row & 7)) << 4));
        size_t aoff = (size_t)(m0 + row) * lda + k0 + j * 8;
        cpasync16(sbase + soff, Ahi + aoff);
        if (TERMS == 2) cpasync16(sbase + 16384 + soff, Alo + aoff);
    }
#pragma unroll
    for (int it = 0; it < NT / 64; it++) {
        int L = it * GTHREADS + tid;
        int row = L >> 3, j = L & 7;
        uint32_t soff = (uint32_t)row * 128 +
                        (((uint32_t)j * 16) ^ (((uint32_t)(row & 7)) << 4));
        int brow = n0 + row;
        brow = brow < Npad ? brow : Npad - 1;
        size_t boff = (size_t)brow * Kpad + k0 + j * 8;
        cpasync16(sbase + SMB + soff, Bh + boff);
    }
    asm volatile("cp.async.commit_group;" ::: "memory");
}

// ---------------- fp16 mma.sync GEMM, tile 128M x NT-N, 3-stage -------------
template <int RELU, int SPLITOUT, int STATS, int TERMS, int NT>
__global__ void __launch_bounds__(GTHREADS, 1)
mma_gemm(const __half* __restrict__ Ahi, const __half* __restrict__ Alo,
         int lda, int Kpad,
         const __half* __restrict__ Bh, int Npad,
         const float* __restrict__ bias, float scale,
         float* __restrict__ C, __half* __restrict__ Chi,
         __half* __restrict__ Clo, int ldc, int Nreal) {
    extern __shared__ char smem[];
    constexpr int JN = NT / 32;
    constexpr int NQ = NT / 64;
    constexpr uint32_t SMB = TERMS * 16384;
    constexpr uint32_t STG = SMB + NT * 128;
    uint32_t sb = smem_u32(smem);
    int tid = threadIdx.x;
    int m0 = blockIdx.y * 128, n0 = blockIdx.x * NT;
    int nchunks = Kpad >> 6;

    gemm_load_stage<TERMS, NT>(sb, tid, m0, n0, 0, Ahi, Alo, lda, Bh, Kpad, Npad);
    gemm_load_stage<TERMS, NT>(sb + STG, tid, m0, n0, 64, Ahi, Alo, lda, Bh, Kpad, Npad);

    int lane = tid & 31, wid = tid >> 5;
    int wm = wid & 3, wn = wid >> 2;

    float acc[2][JN][4];
#pragma unroll
    for (int i = 0; i < 2; i++)
#pragma unroll
        for (int j = 0; j < JN; j++)
#pragma unroll
            for (int r = 0; r < 4; r++) acc[i][j][r] = 0.f;

    uint32_t mask = ((uint32_t)(lane & 7)) << 4;
    uint32_t a_row_off[2];
#pragma unroll
    for (int i = 0; i < 2; i++)
        a_row_off[i] = (uint32_t)(wm * 32 + i * 16 + (lane & 15)) * 128;
    uint32_t a_kb_base = (uint32_t)((lane >> 4) * 16);
    int g = lane >> 3;
    uint32_t b_row_base = (uint32_t)(wn * (NT / 4) + (g >> 1) * 8 + (lane & 7));
    uint32_t b_kb_base = (uint32_t)((g & 1) * 16);

    int slot = 0;
    for (int ch = 0; ch < nchunks; ch++) {
        asm volatile("cp.async.wait_group 1;" ::: "memory");
        __syncthreads();
        if (ch + 2 < nchunks) {
            int ns = slot + 2;
            if (ns >= 3) ns -= 3;
            gemm_load_stage<TERMS, NT>(sb + (uint32_t)ns * STG, tid, m0, n0,
                                       (ch + 2) * 64, Ahi, Alo, lda, Bh, Kpad, Npad);
        } else {
            asm volatile("cp.async.commit_group;" ::: "memory");
        }
        uint32_t st = sb + (uint32_t)slot * STG;
#pragma unroll
        for (int s = 0; s < 4; s++) {
            uint32_t akb = (a_kb_base + s * 32) ^ mask;
            uint32_t bkb = (b_kb_base + s * 32) ^ mask;
            uint32_t ah[2][4], al[2][4];
#pragma unroll
            for (int i = 0; i < 2; i++) {
                LDSM_X4(ah[i][0], ah[i][1], ah[i][2], ah[i][3],
                        st + a_row_off[i] + akb);
                if (TERMS == 2)
                    LDSM_X4(al[i][0], al[i][1], al[i][2], al[i][3],
                            st + 16384 + a_row_off[i] + akb);
            }
#pragma unroll
            for (int q = 0; q < NQ; q++) {
                uint32_t broff = (b_row_base + q * 16) * 128;
                uint32_t bh[4];
                LDSM_X4(bh[0], bh[1], bh[2], bh[3], st + SMB + broff + bkb);
#pragma unroll
                for (int i = 0; i < 2; i++) {
                    MMA16816(acc[i][2 * q], ah[i], bh[0], bh[1]);
                    if (TERMS == 2)
                        MMA16816(acc[i][2 * q], al[i], bh[0], bh[1]);
                    MMA16816(acc[i][2 * q + 1], ah[i], bh[2], bh[3]);
                    if (TERMS == 2)
                        MMA16816(acc[i][2 * q + 1], al[i], bh[2], bh[3]);
                }
            }
        }
        if (++slot == 3) slot = 0;
    }

    // ---- epilogue (+ per-encoder column stats) ----
    int encoff = 0;
    if (STATS) encoff = (m0 >= MPAD) ? EMBD : 0;
#pragma unroll
    for (int j = 0; j < JN; j++) {
        int col = n0 + wn * (NT / 4) + j * 8 + (lane & 3) * 2;
        float b0 = 0.f, b1 = 0.f;
        if (bias != nullptr) {
            b0 = (col < Nreal) ? bias[col] : 0.f;
            b1 = (col + 1 < Nreal) ? bias[col + 1] : 0.f;
        }
        float s0 = 0.f, s1 = 0.f, q0 = 0.f, q1 = 0.f;
#pragma unroll
        for (int i = 0; i < 2; i++) {
            int r0 = m0 + wm * 32 + i * 16 + (lane >> 2);
            float v00 = (col < Nreal) ? (acc[i][j][0] + b0) * scale : 0.f;
            float v01 = (col + 1 < Nreal) ? (acc[i][j][1] + b1) * scale : 0.f;
            float v10 = (col < Nreal) ? (acc[i][j][2] + b0) * scale : 0.f;
            float v11 = (col + 1 < Nreal) ? (acc[i][j][3] + b1) * scale : 0.f;
            if (RELU) {
                v00 = fmaxf(v00, 0.f); v01 = fmaxf(v01, 0.f);
                v10 = fmaxf(v10, 0.f); v11 = fmaxf(v11, 0.f);
            }
            if (STATS) {
                int rr = (r0 >= MPAD) ? r0 - MPAD : r0;
                bool ok0 = (rr < NNODES), ok1 = (rr + 8 < NNODES);
                s0 += (ok0 ? v00 : 0.f) + (ok1 ? v10 : 0.f);
                s1 += (ok0 ? v01 : 0.f) + (ok1 ? v11 : 0.f);
                q0 += (ok0 ? v00 * v00 : 0.f) + (ok1 ? v10 * v10 : 0.f);
                q1 += (ok0 ? v01 * v01 : 0.f) + (ok1 ? v11 * v11 : 0.f);
            }
            if (col < ldc) {
                if (SPLITOUT >= 1) {
                    __half h00 = __float2half_rn(v00);
                    __half h01 = __float2half_rn(v01);
                    __half h10 = __float2half_rn(v10);
                    __half h11 = __float2half_rn(v11);
                    *reinterpret_cast<__half2*>(Chi + (size_t)r0 * ldc + col) =
                        __halves2half2(h00, h01);
                    *reinterpret_cast<__half2*>(Chi + (size_t)(r0 + 8) * ldc + col) =
                        __halves2half2(h10, h11);
                    if (SPLITOUT == 1) {
                        __half2 ll0 = __halves2half2(
                            __float2half_rn(v00 - __half2float(h00)),
                            __float2half_rn(v01 - __half2float(h01)));
                        __half2 ll1 = __halves2half2(
                            __float2half_rn(v10 - __half2float(h10)),
                            __float2half_rn(v11 - __half2float(h11)));
                        *reinterpret_cast<__half2*>(Clo + (size_t)r0 * ldc + col) = ll0;
                        *reinterpret_cast<__half2*>(Clo + (size_t)(r0 + 8) * ldc + col) = ll1;
                    }
                } else {
                    *reinterpret_cast<float2*>(C + (size_t)r0 * ldc + col) =
                        make_float2(v00, v01);
                    *reinterpret_cast<float2*>(C + (size_t)(r0 + 8) * ldc + col) =
                        make_float2(v10, v11);
                }
            }
        }
        if (STATS) {
#pragma unroll
            for (int o = 16; o >= 4; o >>= 1) {
                s0 += __shfl_down_sync(0xffffffffu, s0, o);
                s1 += __shfl_down_sync(0xffffffffu, s1, o);
                q0 += __shfl_down_sync(0xffffffffu, q0, o);
                q1 += __shfl_down_sync(0xffffffffu, q1, o);
            }
            if (lane < 4 && col < Nreal) {
                atomicAdd(&g_bnsum[encoff + col], s0);
                atomicAdd(&g_bnsum[encoff + col + 1], s1);
                atomicAdd(&g_bnss[encoff + col], q0);
                atomicAdd(&g_bnss[encoff + col + 1], q1);
            }
        }
    }
}

// ---------------- BatchNorm finalize, both encoders (self-resets) -----------
__global__ void bn_finalize_kernel(const float* __restrict__ gamma,
                                   const float* __restrict__ beta) {
    int enc = blockIdx.x;
    int c = threadIdx.x;
    if (c >= EMBD) return;
    float sum = g_bnsum[enc * EMBD + c], ss = g_bnss[enc * EMBD + c];
    float mean = sum * (1.0f / NNODES);
    float var = ss * (1.0f / NNODES) - mean * mean;
    float rs = rsqrtf(var + 1e-5f);
    float s = rs * gamma[c];
    g_bnscale[enc * 320 + c] = s;
    g_bnshift[enc * 320 + c] = beta[c] - mean * s;
    g_bnsum[enc * EMBD + c] = 0.f;
    g_bnss[enc * EMBD + c] = 0.f;
}

// ---------------- segment pooling, both encoders ----------------------------
__global__ void pool_seg_kernel(const int* __restrict__ bi0,
                                const int* __restrict__ bi1) {
    __shared__ int s_lo, s_hi;
    int gg = blockIdx.x;
    int enc = gg >= NGRAPHS;
    int g = gg - enc * NGRAPHS;
    const int* bi = enc ? bi1 : bi0;
    if (threadIdx.x == 0) {
        int lo = 0, hi = NNODES;
        while (lo < hi) { int m = (lo + hi) >> 1; if (bi[m] < g) lo = m + 1; else hi = m; }
        s_lo = lo;
        int lo2 = lo, hi2 = NNODES;
        while (lo2 < hi2) { int m = (lo2 + hi2) >> 1; if (bi[m] < g + 1) lo2 = m + 1; else hi2 = m; }
        s_hi = lo2;
    }
    __syncthreads();
    int lo = s_lo, hi = s_hi;
    float inv = 1.0f / fmaxf((float)(hi - lo), 1.0f);
    size_t rbase = (size_t)enc * MPAD;
    int c0 = threadIdx.x, c1 = c0 + 128, c2 = c0 + 256;
    float a0 = 0.f, a1 = 0.f, a2 = 0.f;
    for (int r = lo; r < hi; r++) {
        const __half* row = g_hh + (rbase + r) * LDH;
        a0 += __half2float(row[c0]);
        a1 += __half2float(row[c1]);
        if (c2 < EMBD) a2 += __half2float(row[c2]);
    }
    const float* bsc = g_bnscale + enc * 320;
    const float* bsh = g_bnshift + enc * 320;
    float* dst = g_pool + (size_t)gg * LDH;
    dst[c0] = fmaf(a0 * inv, bsc[c0], bsh[c0]);
    dst[c1] = fmaf(a1 * inv, bsc[c1], bsh[c1]);
    if (c2 < EMBD) dst[c2] = fmaf(a2 * inv, bsc[c2], bsh[c2]);
    else if (c2 < LDH) dst[c2] = 0.f;
}

// ---------------- L2 row normalize ----------------
__global__ void normalize_kernel(float* __restrict__ f) {
    __shared__ float red[4];
    size_t r = blockIdx.x;
    float* row = f + r * LDH;
    float ss = 0.f;
    for (int c = threadIdx.x; c < EMBD; c += 128) {
        float v = row[c];
        ss += v * v;
    }
    for (int o = 16; o; o >>= 1) ss += __shfl_down_sync(0xffffffffu, ss, o);
    if ((threadIdx.x & 31) == 0) red[threadIdx.x >> 5] = ss;
    __syncthreads();
    if (threadIdx.x == 0) red[0] = rsqrtf(red[0] + red[1] + red[2] + red[3]);
    __syncthreads();
    float s = red[0];
    for (int c = threadIdx.x; c < EMBD; c += 128) row[c] *= s;
}

__global__ void labels_kernel(float* __restrict__ out, int extra) {
    int i = blockIdx.x * blockDim.x + threadIdx.x;
    if (i < extra) out[i] = (float)i;
}

// ---------------- host orchestration ----------------
extern "C" void kernel_launch(void* const* d_in, const int* in_sizes, int n_in,
                              void* d_out, int out_size) {
    const float* ae1 = (const float*)d_in[8];
    const float* ae2 = (const float*)d_in[9];
    const float* ee1 = (const float*)d_in[10];
    const float* ee2 = (const float*)d_in[11];
    const float* W1 = (const float*)d_in[12];
    const float* bm1 = (const float*)d_in[13];
    const float* W2 = (const float*)d_in[14];
    const float* bm2 = (const float*)d_in[15];
    const float* gamma = (const float*)d_in[16];
    const float* beta = (const float*)d_in[17];
    const float* bp1 = (const float*)d_in[19];
    const float* bp2 = (const float*)d_in[21];

    float *pool, *feat;
    __half *ahi, *hh, *thi, *phi, *plo, *qlo, *wbuf, *a0, *w1l0;
    cudaGetSymbolAddress((void**)&pool, g_pool);
    cudaGetSymbolAddress((void**)&feat, g_feat);
    cudaGetSymbolAddress((void**)&ahi, g_ahi);
    cudaGetSymbolAddress((void**)&hh, g_hh);
    cudaGetSymbolAddress((void**)&thi, g_thi);
    cudaGetSymbolAddress((void**)&phi, g_phi);
    cudaGetSymbolAddress((void**)&plo, g_plo);
    cudaGetSymbolAddress((void**)&qlo, g_qlo);
    cudaGetSymbolAddress((void**)&wbuf, g_wbuf);
    cudaGetSymbolAddress((void**)&a0, g_a0);
    cudaGetSymbolAddress((void**)&w1l0, g_w1l0);

    const int SM_G1 = 3 * (16384 + 320 * 128);   // TERMS=1, NT=320
    const int SM_P = 3 * (32768 + 320 * 128);    // TERMS=2, NT=320
    const int SM_L = 3 * (32768 + 256 * 128);    // TERMS=2, NT=256
    cudaFuncSetAttribute(mma_gemm<1, 2, 0, 1, 320>,
                         cudaFuncAttributeMaxDynamicSharedMemorySize, SM_G1);
    cudaFuncSetAttribute(mma_gemm<0, 2, 1, 1, 320>,
                         cudaFuncAttributeMaxDynamicSharedMemorySize, SM_G1);
    cudaFuncSetAttribute(mma_gemm<1, 1, 0, 2, 320>,
                         cudaFuncAttributeMaxDynamicSharedMemorySize, SM_P);
    cudaFuncSetAttribute(mma_gemm<0, 0, 0, 2, 320>,
                         cudaFuncAttributeMaxDynamicSharedMemorySize, SM_P);
    cudaFuncSetAttribute(mma_gemm<0, 0, 0, 2, 256>,
                         cudaFuncAttributeMaxDynamicSharedMemorySize, SM_L);

    const int GE = (NEDGES + 255) / 256;
    const int GCN = (2 * NNODES + 255) / 256;
    const int GA = (2 * NNODES * C8 + 255) / 256;
    const int GP2 = (2 * NGRAPHS * LDH + 255) / 256;
    const int GP1 = (NGRAPHS * LDH + 255) / 256;

    const int* x0 = (const int*)d_in[0];
    const int* ei0 = (const int*)d_in[1];
    const int* ea0 = (const int*)d_in[2];
    const int* bi0 = (const int*)d_in[3];
    const int* x1 = (const int*)d_in[4];
    const int* ei1 = (const int*)d_in[5];
    const int* ea1 = (const int*)d_in[6];
    const int* bi1 = (const int*)d_in[7];

    convert_all_kernel<<<2048, 256>>>(W1, W2, (const float*)d_in[18],
                                      (const float*)d_in[20],
                                      ae1, ae2, ee1, ee2);
    edge_count_kernel<<<GE, 256>>>(ei0, ea0, x0, 0, 0);
    edge_count_kernel<<<GE, 256>>>(ei1, ea1, x1, MPAD, NNODES);
    coeff_kernel<<<GCN, 256>>>(x0, x1);

    for (int l = 0; l < NLAYERS; l++) {
        if (l > 0) agg_kernel<<<GA, 256>>>();

        // GEMM1: layer 0 uses compact rank-13 operands (Kpad=64, 1 chunk)
        if (l == 0)
            mma_gemm<1, 2, 0, 1, 320><<<dim3(2, 2 * MTOT), GTHREADS, SM_G1>>>(
                a0, nullptr, 64, 64, w1l0, 640, bm1, 1.0f,
                nullptr, thi, nullptr, LDT, HID);
        else
            mma_gemm<1, 2, 0, 1, 320><<<dim3(2, 2 * MTOT), GTHREADS, SM_G1>>>(
                ahi, nullptr, 320, 320, wbuf + WOFF_W1(l), 640, bm1 + l * HID,
                1.0f, nullptr, thi, nullptr, LDT, HID);

        if (l == 0) {  // combined CSR build, ready before agg(l=1)
            scan_blocks_kernel<<<NB2, 1024>>>();
            scan_add_kernel<<<NB2, 1024>>>();
            fill_csr_kernel<<<GE, 256>>>(ei0, 0);
            fill_csr_kernel<<<GE, 256>>>(ei1, MPAD);
        }

        // GEMM2: thi @ W2 -> h fp16 + per-encoder stats. N=320 exact.
        mma_gemm<0, 2, 1, 1, 320><<<dim3(1, 2 * MTOT), GTHREADS, SM_G1>>>(
            thi, nullptr, LDT, 640, wbuf + WOFF_W2(l), 320, bm2 + l * EMBD,
            1.0f, nullptr, hh, nullptr, LDH, EMBD);
        bn_finalize_kernel<<<2, 512>>>(gamma + l * EMBD, beta + l * EMBD);
    }

    pool_seg_kernel<<<2 * NGRAPHS, 128>>>(bi0, bi1);

    // projection head, M = 8192 (both encoders)
    convert_split_kernel<<<GP2, 256>>>(pool, 2 * NGRAPHS * LDH, phi, plo);
    mma_gemm<1, 1, 0, 2, 320><<<dim3(1, 64), GTHREADS, SM_P>>>(
        phi, plo, 320, 320, wbuf + WOFF_P1, 320, bp1, 1.0f,
        nullptr, thi, qlo, 320, EMBD);
    mma_gemm<0, 0, 0, 2, 320><<<dim3(1, 64), GTHREADS, SM_P>>>(
        thi, qlo, 320, 320, wbuf + WOFF_P2, 320, bp2, 1.0f,
        feat, nullptr, nullptr, LDH, EMBD);

    normalize_kernel<<<2 * NGRAPHS, 128>>>(feat);

    // logits = 25 * f0 @ f1^T
    convert_split_kernel<<<GP1, 256>>>(feat, NGRAPHS * LDH, phi, plo);
    convert_h_kernel<<<GP1, 256>>>(feat + (size_t)NGRAPHS * LDH,
                                   NGRAPHS * LDH, qlo);
    mma_gemm<0, 0, 0, 2, 256><<<dim3(NGRAPHS / 256, NGRAPHS / 128), GTHREADS, SM_L>>>(
        phi, plo, 320, 320, qlo, NGRAPHS,
        nullptr, 25.0f, (float*)d_out, nullptr, nullptr, NGRAPHS, NGRAPHS);

    long long logits_elems = (long long)NGRAPHS * NGRAPHS;
    int extra = (int)((long long)out_size - logits_elems);
    if (extra > 0)
        labels_kernel<<<(extra + 255) / 256, 256>>>(
            (float*)d_out + logits_elems, extra);
}